// round 1
// baseline (speedup 1.0000x reference)
#include <cuda_runtime.h>
#include <math.h>

// Problem constants
constexpr int NB = 32;    // batch
constexpr int NL = 1024;  // La = Lb
constexpr int ND = 256;   // feature dim

// Scratch: attention logits S[b][i][j] (128 MB) + softmax stats
__device__ float g_S[(size_t)NB * NL * NL];
__device__ float g_rowMax[NB * NL];
__device__ float g_rowScale[NB * NL];  // 1/rowSum (0 if empty row)
__device__ float g_colMax[NB * NL];
__device__ float g_colScale[NB * NL];

constexpr int SST = 132;  // smem row stride (floats), keeps float4 alignment

// ---------------------------------------------------------------------------
// K1: S = a @ b^T  per batch.  128x128 tile, K=256 in chunks of 32,
// 256 threads, 8x8 micro-tile per thread (split 4+4 to avoid LDS conflicts).
// ---------------------------------------------------------------------------
__global__ void __launch_bounds__(256) k1_gemm(const float* __restrict__ A,
                                               const float* __restrict__ Bm) {
    __shared__ float As[32][SST];  // [k][i]
    __shared__ float Bs[32][SST];  // [k][j]
    const int bb  = blockIdx.z;
    const int ib0 = blockIdx.y * 128;
    const int jb0 = blockIdx.x * 128;
    const float* Abase = A  + (size_t)(bb * NL + ib0) * ND;
    const float* Bbase = Bm + (size_t)(bb * NL + jb0) * ND;
    const int t  = threadIdx.x;
    const int tx = t & 15, ty = t >> 4;

    float acc[8][8];
#pragma unroll
    for (int i = 0; i < 8; i++)
#pragma unroll
        for (int j = 0; j < 8; j++) acc[i][j] = 0.f;

    for (int kc = 0; kc < ND; kc += 32) {
#pragma unroll
        for (int q = 0; q < 4; q++) {
            int idx = t + 256 * q;     // 0..1023 over 128 rows x 8 float4
            int row = idx >> 3;
            int c4  = (idx & 7) << 2;
            float4 va = *(const float4*)(Abase + (size_t)row * ND + kc + c4);
            As[c4 + 0][row] = va.x; As[c4 + 1][row] = va.y;
            As[c4 + 2][row] = va.z; As[c4 + 3][row] = va.w;
            float4 vb = *(const float4*)(Bbase + (size_t)row * ND + kc + c4);
            Bs[c4 + 0][row] = vb.x; Bs[c4 + 1][row] = vb.y;
            Bs[c4 + 2][row] = vb.z; Bs[c4 + 3][row] = vb.w;
        }
        __syncthreads();
#pragma unroll
        for (int k = 0; k < 32; k++) {
            float ar[8], br[8];
            *(float4*)(ar)     = *(const float4*)&As[k][ty * 4];
            *(float4*)(ar + 4) = *(const float4*)&As[k][64 + ty * 4];
            *(float4*)(br)     = *(const float4*)&Bs[k][tx * 4];
            *(float4*)(br + 4) = *(const float4*)&Bs[k][64 + tx * 4];
#pragma unroll
            for (int i = 0; i < 8; i++)
#pragma unroll
                for (int j = 0; j < 8; j++) acc[i][j] = fmaf(ar[i], br[j], acc[i][j]);
        }
        __syncthreads();
    }
#pragma unroll
    for (int i = 0; i < 8; i++) {
        int row = ib0 + ((i < 4) ? (ty * 4 + i) : (64 + ty * 4 + i - 4));
        float* Sp = g_S + (size_t)(bb * NL + row) * NL + jb0;
        *(float4*)(Sp + tx * 4)      = make_float4(acc[i][0], acc[i][1], acc[i][2], acc[i][3]);
        *(float4*)(Sp + 64 + tx * 4) = make_float4(acc[i][4], acc[i][5], acc[i][6], acc[i][7]);
    }
}

// ---------------------------------------------------------------------------
// K2r: per-row (over j, gated by mask_b) max and 1/sum(exp).  1 warp / row.
// ---------------------------------------------------------------------------
__global__ void __launch_bounds__(256) k2_row(const int* __restrict__ mask_b) {
    const int warp  = threadIdx.x >> 5;
    const int lane  = threadIdx.x & 31;
    const int rowid = blockIdx.x * 8 + warp;  // 0..NB*NL-1
    const int bb    = rowid >> 10;
    const float* Srow = g_S + (size_t)rowid * NL;
    const int* mb = mask_b + bb * NL;

    float m = -INFINITY;
    for (int j = lane * 4; j < NL; j += 128) {
        float4 v = *(const float4*)(Srow + j);
        int4  mk = *(const int4*)(mb + j);
        if (mk.x) m = fmaxf(m, v.x);
        if (mk.y) m = fmaxf(m, v.y);
        if (mk.z) m = fmaxf(m, v.z);
        if (mk.w) m = fmaxf(m, v.w);
    }
#pragma unroll
    for (int o = 16; o > 0; o >>= 1) m = fmaxf(m, __shfl_xor_sync(0xffffffffu, m, o));

    float s = 0.f;
    if (m != -INFINITY) {
        for (int j = lane * 4; j < NL; j += 128) {
            float4 v = *(const float4*)(Srow + j);
            int4  mk = *(const int4*)(mb + j);
            if (mk.x) s += __expf(v.x - m);
            if (mk.y) s += __expf(v.y - m);
            if (mk.z) s += __expf(v.z - m);
            if (mk.w) s += __expf(v.w - m);
        }
    }
#pragma unroll
    for (int o = 16; o > 0; o >>= 1) s += __shfl_xor_sync(0xffffffffu, s, o);

    if (lane == 0) {
        if (m == -INFINITY) { g_rowMax[rowid] = 0.f; g_rowScale[rowid] = 0.f; }
        else                { g_rowMax[rowid] = m;   g_rowScale[rowid] = 1.f / s; }
    }
}

// ---------------------------------------------------------------------------
// K2c: per-column (over i, gated by mask_a) online max/sum.
// CTA = (64-col block, batch); 256 threads = 64 cols x 4 row-quarters.
// ---------------------------------------------------------------------------
__global__ void __launch_bounds__(256) k2_col(const int* __restrict__ mask_a) {
    const int bb  = blockIdx.y;
    const int jb0 = blockIdx.x * 64;
    const int t   = threadIdx.x;
    const int cl  = t & 63;
    const int q   = t >> 6;  // 0..3
    const int* ma = mask_a + bb * NL;
    const float* Sbase = g_S + (size_t)bb * NL * NL;

    float m = -INFINITY, s = 0.f;
    const int i0 = q * 256;
    for (int i = i0; i < i0 + 256; i++) {
        if (!ma[i]) continue;
        float v = Sbase[(size_t)i * NL + jb0 + cl];
        if (v > m) { s = s * __expf(m - v) + 1.f; m = v; }
        else       { s += __expf(v - m); }
    }
    __shared__ float sm[4][64], ss[4][64];
    sm[q][cl] = m; ss[q][cl] = s;
    __syncthreads();
    if (t < 64) {
        float M = sm[0][t], S = ss[0][t];
#pragma unroll
        for (int r = 1; r < 4; r++) {
            float m2 = sm[r][t], s2 = ss[r][t];
            float nm = fmaxf(M, m2);
            if (nm == -INFINITY) continue;  // both empty
            S = S * __expf(M - nm) + s2 * __expf(m2 - nm);
            M = nm;
        }
        int j = bb * NL + jb0 + t;
        if (M == -INFINITY) { g_colMax[j] = 0.f; g_colScale[j] = 0.f; }
        else                { g_colMax[j] = M;   g_colScale[j] = 1.f / S; }
    }
}

// ---------------------------------------------------------------------------
// K3a: attended_a = W @ b, W regenerated on the fly from S + row stats.
// Tile: 128 rows(i) x 128 cols(d), K over j in chunks of 32.
// ---------------------------------------------------------------------------
__global__ void __launch_bounds__(256) k3a(const float* __restrict__ Bm,
                                           const int* __restrict__ mask_a,
                                           const int* __restrict__ mask_b,
                                           float* __restrict__ outA) {
    __shared__ float Ws[32][SST];  // [k=j][i]
    __shared__ float Bs[32][SST];  // [k=j][d]
    __shared__ float rM[128], rSc[128];
    const int bb  = blockIdx.z;
    const int ib0 = blockIdx.y * 128;
    const int db0 = blockIdx.x * 128;
    const int t   = threadIdx.x;
    const int tx  = t & 15, ty = t >> 4;

    if (t < 128) {
        int r = bb * NL + ib0 + t;
        rM[t]  = g_rowMax[r];
        rSc[t] = mask_a[r] ? g_rowScale[r] : 0.f;
    }
    __syncthreads();

    float acc[8][8];
#pragma unroll
    for (int i = 0; i < 8; i++)
#pragma unroll
        for (int j = 0; j < 8; j++) acc[i][j] = 0.f;

    const float* Sbase = g_S + (size_t)(bb * NL + ib0) * NL;
    const float* Bbase = Bm + (size_t)bb * NL * ND + db0;
    const int* mb = mask_b + bb * NL;

    for (int kc = 0; kc < NL; kc += 32) {
#pragma unroll
        for (int q = 0; q < 4; q++) {
            int idx = t + 256 * q;
            int row = idx >> 3;
            int c4  = (idx & 7) << 2;
            float4 v = *(const float4*)(Sbase + (size_t)row * NL + kc + c4);
            int4  mk = *(const int4*)(mb + kc + c4);
            float mr = rM[row];
            Ws[c4 + 0][row] = mk.x ? __expf(v.x - mr) : 0.f;
            Ws[c4 + 1][row] = mk.y ? __expf(v.y - mr) : 0.f;
            Ws[c4 + 2][row] = mk.z ? __expf(v.z - mr) : 0.f;
            Ws[c4 + 3][row] = mk.w ? __expf(v.w - mr) : 0.f;
        }
#pragma unroll
        for (int q = 0; q < 4; q++) {
            int idx = t + 256 * q;     // 32 rows x 32 float4
            int row = idx >> 5;
            int c4  = (idx & 31) << 2;
            float4 v = *(const float4*)(Bbase + (size_t)(kc + row) * ND + c4);
            *(float4*)&Bs[row][c4] = v;
        }
        __syncthreads();
#pragma unroll
        for (int k = 0; k < 32; k++) {
            float ar[8], br[8];
            *(float4*)(ar)     = *(const float4*)&Ws[k][ty * 4];
            *(float4*)(ar + 4) = *(const float4*)&Ws[k][64 + ty * 4];
            *(float4*)(br)     = *(const float4*)&Bs[k][tx * 4];
            *(float4*)(br + 4) = *(const float4*)&Bs[k][64 + tx * 4];
#pragma unroll
            for (int i = 0; i < 8; i++)
#pragma unroll
                for (int j = 0; j < 8; j++) acc[i][j] = fmaf(ar[i], br[j], acc[i][j]);
        }
        __syncthreads();
    }
#pragma unroll
    for (int i = 0; i < 8; i++) {
        int rl = (i < 4) ? (ty * 4 + i) : (64 + ty * 4 + i - 4);
        float sc = rSc[rl];
        float* Op = outA + (size_t)(bb * NL + ib0 + rl) * ND + db0;
        *(float4*)(Op + tx * 4) =
            make_float4(acc[i][0] * sc, acc[i][1] * sc, acc[i][2] * sc, acc[i][3] * sc);
        *(float4*)(Op + 64 + tx * 4) =
            make_float4(acc[i][4] * sc, acc[i][5] * sc, acc[i][6] * sc, acc[i][7] * sc);
    }
}

// ---------------------------------------------------------------------------
// K3b: attended_b[j,:] = sum_i exp(S_ij - cM_j)/cZ_j * ma_i * a[i,:]
// Tile: 128 rows(j) x 128 cols(d), K over i in chunks of 32.
// S tile is naturally [k=i][j] row-major -> no transpose needed.
// ---------------------------------------------------------------------------
__global__ void __launch_bounds__(256) k3b(const float* __restrict__ Am,
                                           const int* __restrict__ mask_a,
                                           const int* __restrict__ mask_b,
                                           float* __restrict__ outB) {
    __shared__ float Ws[32][SST];  // [k=i][j]
    __shared__ float Vs[32][SST];  // [k=i][d]
    __shared__ float cM[128], cSc[128];
    const int bb  = blockIdx.z;
    const int jb0 = blockIdx.y * 128;
    const int db0 = blockIdx.x * 128;
    const int t   = threadIdx.x;
    const int tx  = t & 15, ty = t >> 4;

    if (t < 128) {
        int j = bb * NL + jb0 + t;
        cM[t]  = g_colMax[j];
        cSc[t] = mask_b[j] ? g_colScale[j] : 0.f;
    }
    __syncthreads();

    float acc[8][8];
#pragma unroll
    for (int i = 0; i < 8; i++)
#pragma unroll
        for (int j = 0; j < 8; j++) acc[i][j] = 0.f;

    const float* Sbase = g_S + (size_t)bb * NL * NL + jb0;
    const float* Abase = Am + (size_t)bb * NL * ND + db0;
    const int* ma = mask_a + bb * NL;

    for (int kc = 0; kc < NL; kc += 32) {
#pragma unroll
        for (int q = 0; q < 4; q++) {
            int idx = t + 256 * q;     // 32 rows(i) x 32 float4(j)
            int row = idx >> 5;
            int c4  = (idx & 31) << 2;
            float4 v = *(const float4*)(Sbase + (size_t)(kc + row) * NL + c4);
            float4 w;
            if (ma[kc + row]) {
                w.x = __expf(v.x - cM[c4 + 0]);
                w.y = __expf(v.y - cM[c4 + 1]);
                w.z = __expf(v.z - cM[c4 + 2]);
                w.w = __expf(v.w - cM[c4 + 3]);
            } else {
                w = make_float4(0.f, 0.f, 0.f, 0.f);
            }
            *(float4*)&Ws[row][c4] = w;
        }
#pragma unroll
        for (int q = 0; q < 4; q++) {
            int idx = t + 256 * q;     // 32 rows(i) x 32 float4(d)
            int row = idx >> 5;
            int c4  = (idx & 31) << 2;
            float4 v = *(const float4*)(Abase + (size_t)(kc + row) * ND + c4);
            *(float4*)&Vs[row][c4] = v;
        }
        __syncthreads();
#pragma unroll
        for (int k = 0; k < 32; k++) {
            float ar[8], br[8];
            *(float4*)(ar)     = *(const float4*)&Ws[k][ty * 4];
            *(float4*)(ar + 4) = *(const float4*)&Ws[k][64 + ty * 4];
            *(float4*)(br)     = *(const float4*)&Vs[k][tx * 4];
            *(float4*)(br + 4) = *(const float4*)&Vs[k][64 + tx * 4];
#pragma unroll
            for (int i = 0; i < 8; i++)
#pragma unroll
                for (int j = 0; j < 8; j++) acc[i][j] = fmaf(ar[i], br[j], acc[i][j]);
        }
        __syncthreads();
    }
#pragma unroll
    for (int i = 0; i < 8; i++) {
        int rl = (i < 4) ? (ty * 4 + i) : (64 + ty * 4 + i - 4);
        float sc = cSc[rl];
        float* Op = outB + (size_t)(bb * NL + jb0 + rl) * ND + db0;
        *(float4*)(Op + tx * 4) =
            make_float4(acc[i][0] * sc, acc[i][1] * sc, acc[i][2] * sc, acc[i][3] * sc);
        *(float4*)(Op + 64 + tx * 4) =
            make_float4(acc[i][4] * sc, acc[i][5] * sc, acc[i][6] * sc, acc[i][7] * sc);
    }
}

// ---------------------------------------------------------------------------
extern "C" void kernel_launch(void* const* d_in, const int* in_sizes, int n_in,
                              void* d_out, int out_size) {
    const float* a      = (const float*)d_in[0];
    const float* b      = (const float*)d_in[1];
    const int*   mask_a = (const int*)d_in[2];
    const int*   mask_b = (const int*)d_in[3];
    float* outA = (float*)d_out;
    float* outB = outA + (size_t)NB * NL * ND;

    k1_gemm<<<dim3(8, 8, NB), 256>>>(a, b);
    k2_row<<<NB * NL / 8, 256>>>(mask_b);
    k2_col<<<dim3(NL / 64, NB), 256>>>(mask_a);
    k3a<<<dim3(ND / 128, 8, NB), 256>>>(b, mask_a, mask_b, outA);
    k3b<<<dim3(ND / 128, 8, NB), 256>>>(a, mask_a, mask_b, outB);
}

// round 2
// speedup vs baseline: 2.1590x; 2.1590x over previous
#include <cuda_runtime.h>
#include <math.h>

// Problem constants
constexpr int NB = 32;    // batch
constexpr int NL = 1024;  // La = Lb
constexpr int ND = 256;   // feature dim

// Scratch: compact logits S[b][ic][jc] (stride NL) + stats + index lists
__device__ float g_S[(size_t)NB * NL * NL];
__device__ float g_rowMax[NB * NL];
__device__ float g_rowScale[NB * NL];
__device__ float g_colMax[NB * NL];
__device__ float g_colScale[NB * NL];
__device__ int   g_idxA[NB * NL];
__device__ int   g_idxB[NB * NL];
__device__ int   g_cntA[NB];
__device__ int   g_cntB[NB];

constexpr int SST = 132;  // smem row stride (floats), float4-aligned

// ---------------------------------------------------------------------------
// K0: per-batch mask compaction. blockIdx.x: [0,32)=mask_a, [32,64)=mask_b.
// Builds idx list of unmasked positions, padded to 1024 with last valid idx.
// ---------------------------------------------------------------------------
__global__ void __launch_bounds__(1024) k0_compact(const int* __restrict__ mask_a,
                                                   const int* __restrict__ mask_b) {
    const int which = blockIdx.x >> 5;
    const int bb    = blockIdx.x & 31;
    const int* m = (which ? mask_b : mask_a) + bb * NL;
    int* idx = (which ? g_idxB : g_idxA) + bb * NL;
    int* cnt = which ? g_cntB : g_cntA;
    const int t = threadIdx.x, lane = t & 31, w = t >> 5;

    int mv = (m[t] != 0);
    unsigned bal = __ballot_sync(0xffffffffu, mv);
    int pw = __popc(bal & ((1u << lane) - 1));
    __shared__ int wc[32];
    if (lane == 0) wc[w] = __popc(bal);
    __syncthreads();
    if (t < 32) {
        int v = wc[t];
#pragma unroll
        for (int o = 1; o < 32; o <<= 1) {
            int u = __shfl_up_sync(0xffffffffu, v, o);
            if (lane >= o) v += u;
        }
        wc[t] = v;  // inclusive scan
    }
    __syncthreads();
    const int base  = (w == 0) ? 0 : wc[w - 1];
    const int total = wc[31];
    if (mv) idx[base + pw] = t;
    if (t == 0) cnt[bb] = total;
    __syncthreads();
    __shared__ int lastIdx;
    if (t == 0) lastIdx = (total > 0) ? idx[total - 1] : 0;
    __syncthreads();
    if (t >= total) idx[t] = lastIdx;
}

// ---------------------------------------------------------------------------
// K1: S_compact = a[idxA] @ b[idxB]^T per batch. 128x128 tile, K=256.
// ---------------------------------------------------------------------------
__global__ void __launch_bounds__(256) k1_gemm(const float* __restrict__ A,
                                               const float* __restrict__ Bm) {
    const int bb  = blockIdx.z;
    const int ib0 = blockIdx.y * 128;
    const int jb0 = blockIdx.x * 128;
    const int na  = g_cntA[bb];
    const int nb  = g_cntB[bb];
    if (ib0 >= na || jb0 >= nb) return;

    __shared__ float As[32][SST];  // [k][i]
    __shared__ float Bs[32][SST];  // [k][j]
    __shared__ int rA[128], rB[128];
    const int t  = threadIdx.x;
    const int tx = t & 15, ty = t >> 4;

    if (t < 128)      rA[t]       = g_idxA[bb * NL + ib0 + t];
    else              rB[t - 128] = g_idxB[bb * NL + jb0 + (t - 128)];
    __syncthreads();

    float acc[8][8];
#pragma unroll
    for (int i = 0; i < 8; i++)
#pragma unroll
        for (int j = 0; j < 8; j++) acc[i][j] = 0.f;

    for (int kc = 0; kc < ND; kc += 32) {
#pragma unroll
        for (int q = 0; q < 4; q++) {
            int idx = t + 256 * q;     // 128 rows x 8 float4
            int row = idx >> 3;
            int c4  = (idx & 7) << 2;
            float4 va = *(const float4*)(A + (size_t)(bb * NL + rA[row]) * ND + kc + c4);
            As[c4 + 0][row] = va.x; As[c4 + 1][row] = va.y;
            As[c4 + 2][row] = va.z; As[c4 + 3][row] = va.w;
            float4 vb = *(const float4*)(Bm + (size_t)(bb * NL + rB[row]) * ND + kc + c4);
            Bs[c4 + 0][row] = vb.x; Bs[c4 + 1][row] = vb.y;
            Bs[c4 + 2][row] = vb.z; Bs[c4 + 3][row] = vb.w;
        }
        __syncthreads();
#pragma unroll
        for (int k = 0; k < 32; k++) {
            float ar[8], br[8];
            *(float4*)(ar)     = *(const float4*)&As[k][ty * 4];
            *(float4*)(ar + 4) = *(const float4*)&As[k][64 + ty * 4];
            *(float4*)(br)     = *(const float4*)&Bs[k][tx * 4];
            *(float4*)(br + 4) = *(const float4*)&Bs[k][64 + tx * 4];
#pragma unroll
            for (int i = 0; i < 8; i++)
#pragma unroll
                for (int j = 0; j < 8; j++) acc[i][j] = fmaf(ar[i], br[j], acc[i][j]);
        }
        __syncthreads();
    }
#pragma unroll
    for (int i = 0; i < 8; i++) {
        int row = ib0 + ((i < 4) ? (ty * 4 + i) : (64 + ty * 4 + i - 4));
        float* Sp = g_S + (size_t)(bb * NL + row) * NL + jb0;
        *(float4*)(Sp + tx * 4)      = make_float4(acc[i][0], acc[i][1], acc[i][2], acc[i][3]);
        *(float4*)(Sp + 64 + tx * 4) = make_float4(acc[i][4], acc[i][5], acc[i][6], acc[i][7]);
    }
}

// ---------------------------------------------------------------------------
// K2r: per-compact-row max and 1/sum(exp) over [0, nb).  1 warp / row.
// ---------------------------------------------------------------------------
__global__ void __launch_bounds__(256) k2_row() {
    const int warp  = threadIdx.x >> 5;
    const int lane  = threadIdx.x & 31;
    const int rowid = blockIdx.x * 8 + warp;
    const int bb    = rowid >> 10;
    const int r     = rowid & (NL - 1);
    if (r >= g_cntA[bb]) return;
    const int nb = g_cntB[bb];
    const float* Srow = g_S + (size_t)rowid * NL;

    const int nb4 = nb & ~3;
    float m = -INFINITY;
    for (int j = lane * 4; j < nb4; j += 128) {
        float4 v = *(const float4*)(Srow + j);
        m = fmaxf(m, fmaxf(fmaxf(v.x, v.y), fmaxf(v.z, v.w)));
    }
    for (int j = nb4 + lane; j < nb; j += 32) m = fmaxf(m, Srow[j]);
#pragma unroll
    for (int o = 16; o > 0; o >>= 1) m = fmaxf(m, __shfl_xor_sync(0xffffffffu, m, o));

    float s = 0.f;
    if (m != -INFINITY) {
        for (int j = lane * 4; j < nb4; j += 128) {
            float4 v = *(const float4*)(Srow + j);
            s += __expf(v.x - m) + __expf(v.y - m) + __expf(v.z - m) + __expf(v.w - m);
        }
        for (int j = nb4 + lane; j < nb; j += 32) s += __expf(Srow[j] - m);
    }
#pragma unroll
    for (int o = 16; o > 0; o >>= 1) s += __shfl_xor_sync(0xffffffffu, s, o);

    if (lane == 0) {
        if (m == -INFINITY) { g_rowMax[rowid] = 0.f; g_rowScale[rowid] = 0.f; }
        else                { g_rowMax[rowid] = m;   g_rowScale[rowid] = 1.f / s; }
    }
}

// ---------------------------------------------------------------------------
// K2c: per-compact-column online max/sum over i in [0, na).
// ---------------------------------------------------------------------------
__global__ void __launch_bounds__(256) k2_col() {
    const int bb  = blockIdx.y;
    const int jb0 = blockIdx.x * 64;
    const int na  = g_cntA[bb];
    const int nb  = g_cntB[bb];
    if (jb0 >= nb) return;
    const int t  = threadIdx.x;
    const int cl = t & 63;
    const int q  = t >> 6;
    const float* Sbase = g_S + (size_t)bb * NL * NL;

    float m = -INFINITY, s = 0.f;
    const int i0 = q * 256;
    const int i1 = min(i0 + 256, na);
    for (int i = i0; i < i1; i++) {
        float v = Sbase[(size_t)i * NL + jb0 + cl];
        if (v > m) { s = s * __expf(m - v) + 1.f; m = v; }
        else       { s += __expf(v - m); }
    }
    __shared__ float sm[4][64], ss[4][64];
    sm[q][cl] = m; ss[q][cl] = s;
    __syncthreads();
    if (t < 64 && jb0 + t < nb) {
        float M = sm[0][t], S = ss[0][t];
#pragma unroll
        for (int r = 1; r < 4; r++) {
            float m2 = sm[r][t], s2 = ss[r][t];
            float nm = fmaxf(M, m2);
            if (nm == -INFINITY) continue;
            S = S * __expf(M - nm) + s2 * __expf(m2 - nm);
            M = nm;
        }
        int j = bb * NL + jb0 + t;
        if (M == -INFINITY) { g_colMax[j] = 0.f; g_colScale[j] = 0.f; }
        else                { g_colMax[j] = M;   g_colScale[j] = 1.f / S; }
    }
}

// ---------------------------------------------------------------------------
// K3a: attended_a[idxA[i],:] = (1/Z_i) * sum_{j<nb} exp(S_ij - M_i) b[idxB[j],:]
// Tile: 128 compact rows(i) x 128 cols(d), K over compact j.
// ---------------------------------------------------------------------------
__global__ void __launch_bounds__(256) k3a(const float* __restrict__ Bm,
                                           float* __restrict__ outA) {
    const int bb  = blockIdx.z;
    const int ib0 = blockIdx.y * 128;
    const int db0 = blockIdx.x * 128;
    const int na  = g_cntA[bb];
    const int nb  = g_cntB[bb];
    if (ib0 >= na) return;

    __shared__ float Ws[32][SST];  // [k=j][i]
    __shared__ float Bs[32][SST];  // [k=j][d]
    __shared__ float rM[128], rSc[128];
    const int t  = threadIdx.x;
    const int tx = t & 15, ty = t >> 4;

    if (t < 128) {
        int r = bb * NL + ib0 + t;
        rM[t]  = g_rowMax[r];
        rSc[t] = g_rowScale[r];
    }
    __syncthreads();

    float acc[8][8];
#pragma unroll
    for (int i = 0; i < 8; i++)
#pragma unroll
        for (int j = 0; j < 8; j++) acc[i][j] = 0.f;

    const float* Sbase = g_S + (size_t)(bb * NL + ib0) * NL;
    const int*   idxB  = g_idxB + bb * NL;
    const int    kend  = (nb + 31) & ~31;

    for (int kc = 0; kc < kend; kc += 32) {
#pragma unroll
        for (int q = 0; q < 4; q++) {
            int idx = t + 256 * q;
            int row = idx >> 3;
            int c4  = (idx & 7) << 2;
            float4 v = *(const float4*)(Sbase + (size_t)row * NL + kc + c4);
            float mr = rM[row];
            Ws[c4 + 0][row] = (kc + c4 + 0 < nb) ? __expf(v.x - mr) : 0.f;
            Ws[c4 + 1][row] = (kc + c4 + 1 < nb) ? __expf(v.y - mr) : 0.f;
            Ws[c4 + 2][row] = (kc + c4 + 2 < nb) ? __expf(v.z - mr) : 0.f;
            Ws[c4 + 3][row] = (kc + c4 + 3 < nb) ? __expf(v.w - mr) : 0.f;
        }
#pragma unroll
        for (int q = 0; q < 4; q++) {
            int idx = t + 256 * q;     // 32 rows(j) x 32 float4(d)
            int row = idx >> 5;
            int c4  = (idx & 31) << 2;
            int gb  = idxB[kc + row];  // padded -> last valid (weight is 0)
            float4 v = *(const float4*)(Bm + (size_t)(bb * NL + gb) * ND + db0 + c4);
            *(float4*)&Bs[row][c4] = v;
        }
        __syncthreads();
#pragma unroll
        for (int k = 0; k < 32; k++) {
            float ar[8], br[8];
            *(float4*)(ar)     = *(const float4*)&Ws[k][ty * 4];
            *(float4*)(ar + 4) = *(const float4*)&Ws[k][64 + ty * 4];
            *(float4*)(br)     = *(const float4*)&Bs[k][tx * 4];
            *(float4*)(br + 4) = *(const float4*)&Bs[k][64 + tx * 4];
#pragma unroll
            for (int i = 0; i < 8; i++)
#pragma unroll
                for (int j = 0; j < 8; j++) acc[i][j] = fmaf(ar[i], br[j], acc[i][j]);
        }
        __syncthreads();
    }
    const int* idxA = g_idxA + bb * NL;
#pragma unroll
    for (int i = 0; i < 8; i++) {
        int rl = (i < 4) ? (ty * 4 + i) : (64 + ty * 4 + i - 4);
        if (ib0 + rl >= na) continue;
        float sc = rSc[rl];
        float* Op = outA + (size_t)(bb * NL + idxA[ib0 + rl]) * ND + db0;
        *(float4*)(Op + tx * 4) =
            make_float4(acc[i][0] * sc, acc[i][1] * sc, acc[i][2] * sc, acc[i][3] * sc);
        *(float4*)(Op + 64 + tx * 4) =
            make_float4(acc[i][4] * sc, acc[i][5] * sc, acc[i][6] * sc, acc[i][7] * sc);
    }
}

// ---------------------------------------------------------------------------
// K3b: attended_b[idxB[j],:] = (1/Z_j) * sum_{i<na} exp(S_ij - cM_j) a[idxA[i],:]
// Tile: 128 compact rows(j) x 128 cols(d), K over compact i.
// ---------------------------------------------------------------------------
__global__ void __launch_bounds__(256) k3b(const float* __restrict__ Am,
                                           float* __restrict__ outB) {
    const int bb  = blockIdx.z;
    const int jb0 = blockIdx.y * 128;
    const int db0 = blockIdx.x * 128;
    const int na  = g_cntA[bb];
    const int nb  = g_cntB[bb];
    if (jb0 >= nb) return;

    __shared__ float Ws[32][SST];  // [k=i][j]
    __shared__ float Vs[32][SST];  // [k=i][d]
    __shared__ float cM[128], cSc[128];
    const int t  = threadIdx.x;
    const int tx = t & 15, ty = t >> 4;

    if (t < 128) {
        int j = bb * NL + jb0 + t;
        cM[t]  = g_colMax[j];
        cSc[t] = g_colScale[j];
    }
    __syncthreads();

    float acc[8][8];
#pragma unroll
    for (int i = 0; i < 8; i++)
#pragma unroll
        for (int j = 0; j < 8; j++) acc[i][j] = 0.f;

    const float* Sbase = g_S + (size_t)bb * NL * NL + jb0;
    const int*   idxA  = g_idxA + bb * NL;
    const int    kend  = (na + 31) & ~31;

    for (int kc = 0; kc < kend; kc += 32) {
#pragma unroll
        for (int q = 0; q < 4; q++) {
            int idx = t + 256 * q;     // 32 rows(i) x 32 float4(j)
            int row = idx >> 5;
            int c4  = (idx & 31) << 2;
            float4 w;
            if (kc + row < na) {
                float4 v = *(const float4*)(Sbase + (size_t)(kc + row) * NL + c4);
                w.x = __expf(v.x - cM[c4 + 0]);
                w.y = __expf(v.y - cM[c4 + 1]);
                w.z = __expf(v.z - cM[c4 + 2]);
                w.w = __expf(v.w - cM[c4 + 3]);
            } else {
                w = make_float4(0.f, 0.f, 0.f, 0.f);
            }
            *(float4*)&Ws[row][c4] = w;
        }
#pragma unroll
        for (int q = 0; q < 4; q++) {
            int idx = t + 256 * q;     // 32 rows(i) x 32 float4(d)
            int row = idx >> 5;
            int c4  = (idx & 31) << 2;
            int ga  = idxA[min(kc + row, NL - 1)];
            float4 v = *(const float4*)(Am + (size_t)(bb * NL + ga) * ND + db0 + c4);
            *(float4*)&Vs[row][c4] = v;
        }
        __syncthreads();
#pragma unroll
        for (int k = 0; k < 32; k++) {
            float ar[8], br[8];
            *(float4*)(ar)     = *(const float4*)&Ws[k][ty * 4];
            *(float4*)(ar + 4) = *(const float4*)&Ws[k][64 + ty * 4];
            *(float4*)(br)     = *(const float4*)&Vs[k][tx * 4];
            *(float4*)(br + 4) = *(const float4*)&Vs[k][64 + tx * 4];
#pragma unroll
            for (int i = 0; i < 8; i++)
#pragma unroll
                for (int j = 0; j < 8; j++) acc[i][j] = fmaf(ar[i], br[j], acc[i][j]);
        }
        __syncthreads();
    }
    const int* idxB = g_idxB + bb * NL;
#pragma unroll
    for (int i = 0; i < 8; i++) {
        int rl = (i < 4) ? (ty * 4 + i) : (64 + ty * 4 + i - 4);
        if (jb0 + rl >= nb) continue;
        float sc = cSc[rl];
        float* Op = outB + (size_t)(bb * NL + idxB[jb0 + rl]) * ND + db0;
        *(float4*)(Op + tx * 4) =
            make_float4(acc[i][0] * sc, acc[i][1] * sc, acc[i][2] * sc, acc[i][3] * sc);
        *(float4*)(Op + 64 + tx * 4) =
            make_float4(acc[i][4] * sc, acc[i][5] * sc, acc[i][6] * sc, acc[i][7] * sc);
    }
}

// ---------------------------------------------------------------------------
extern "C" void kernel_launch(void* const* d_in, const int* in_sizes, int n_in,
                              void* d_out, int out_size) {
    const float* a      = (const float*)d_in[0];
    const float* b      = (const float*)d_in[1];
    const int*   mask_a = (const int*)d_in[2];
    const int*   mask_b = (const int*)d_in[3];
    float* outA = (float*)d_out;
    float* outB = outA + (size_t)NB * NL * ND;

    // Masked rows of both outputs are exactly zero in the reference.
    cudaMemsetAsync(d_out, 0, (size_t)out_size * sizeof(float));

    k0_compact<<<64, 1024>>>(mask_a, mask_b);
    k1_gemm<<<dim3(8, 8, NB), 256>>>(a, b);
    k2_row<<<NB * NL / 8, 256>>>();
    k2_col<<<dim3(NL / 64, NB), 256>>>();
    k3a<<<dim3(ND / 128, 8, NB), 256>>>(b, outA);
    k3b<<<dim3(ND / 128, 8, NB), 256>>>(a, outB);
}

// round 4
// speedup vs baseline: 3.2700x; 1.5146x over previous
#include <cuda_runtime.h>
#include <cuda_bf16.h>
#include <math.h>
#include <cstdint>

// Problem constants
constexpr int NB = 32;    // batch
constexpr int NL = 1024;  // La = Lb
constexpr int ND = 256;   // feature dim

// Scratch
__device__ float g_S [(size_t)NB * NL * NL];   // logits, compact [i][j]
__device__ float g_ST[(size_t)NB * NL * NL];   // logits transposed, compact [j][i]
__device__ float g_rowMax[NB * NL];
__device__ float g_rowScale[NB * NL];
__device__ float g_colMax[NB * NL];
__device__ float g_colScale[NB * NL];
__device__ int   g_idxA[NB * NL];
__device__ int   g_idxB[NB * NL];
__device__ int   g_cntA[NB];
__device__ int   g_cntB[NB];

// Compacted bf16 hi/lo copies of a, b (row = compact position), plus transposed.
__device__ __nv_bfloat16 g_Ahi [(size_t)NB * NL * ND];
__device__ __nv_bfloat16 g_Alo [(size_t)NB * NL * ND];
__device__ __nv_bfloat16 g_Bhi [(size_t)NB * NL * ND];
__device__ __nv_bfloat16 g_Blo [(size_t)NB * NL * ND];
__device__ __nv_bfloat16 g_AhiT[(size_t)NB * ND * NL];   // [d][i_compact]
__device__ __nv_bfloat16 g_AloT[(size_t)NB * ND * NL];
__device__ __nv_bfloat16 g_BhiT[(size_t)NB * ND * NL];   // [d][j_compact]
__device__ __nv_bfloat16 g_BloT[(size_t)NB * ND * NL];

constexpr int RS = 40;  // smem bf16 row stride (32 data + 8 pad), conflict-free quads

// m16n8k16 bf16 MMA, fp32 accumulate (sm_80+ PTX -> legacy HMMA on sm_103a)
__device__ __forceinline__ void mma_bf16(float* c, uint32_t a0, uint32_t a1,
                                         uint32_t a2, uint32_t a3,
                                         uint32_t b0, uint32_t b1) {
    asm volatile(
        "mma.sync.aligned.m16n8k16.row.col.f32.bf16.bf16.f32 "
        "{%0,%1,%2,%3}, {%4,%5,%6,%7}, {%8,%9}, {%0,%1,%2,%3};"
        : "+f"(c[0]), "+f"(c[1]), "+f"(c[2]), "+f"(c[3])
        : "r"(a0), "r"(a1), "r"(a2), "r"(a3), "r"(b0), "r"(b1));
}

__device__ __forceinline__ uint32_t lds32(const __nv_bfloat16* p) {
    return *(const uint32_t*)p;
}

// ---------------------------------------------------------------------------
// K0: per-batch mask compaction (idx padded to 1024 with last valid index).
// ---------------------------------------------------------------------------
__global__ void __launch_bounds__(1024) k0_compact(const int* __restrict__ mask_a,
                                                   const int* __restrict__ mask_b) {
    const int which = blockIdx.x >> 5;
    const int bb    = blockIdx.x & 31;
    const int* m = (which ? mask_b : mask_a) + bb * NL;
    int* idx = (which ? g_idxB : g_idxA) + bb * NL;
    int* cnt = which ? g_cntB : g_cntA;
    const int t = threadIdx.x, lane = t & 31, w = t >> 5;

    int mv = (m[t] != 0);
    unsigned bal = __ballot_sync(0xffffffffu, mv);
    int pw = __popc(bal & ((1u << lane) - 1));
    __shared__ int wc[32];
    if (lane == 0) wc[w] = __popc(bal);
    __syncthreads();
    if (t < 32) {
        int v = wc[t];
#pragma unroll
        for (int o = 1; o < 32; o <<= 1) {
            int u = __shfl_up_sync(0xffffffffu, v, o);
            if (lane >= o) v += u;
        }
        wc[t] = v;
    }
    __syncthreads();
    const int base  = (w == 0) ? 0 : wc[w - 1];
    const int total = wc[31];
    if (mv) idx[base + pw] = t;
    if (t == 0) cnt[bb] = total;
    __syncthreads();
    __shared__ int lastIdx;
    if (t == 0) lastIdx = (total > 0) ? idx[total - 1] : 0;
    __syncthreads();
    if (t >= total) idx[t] = lastIdx;
}

// ---------------------------------------------------------------------------
// KC: gather-compact + fp32->bf16 hi/lo split + transpose.
// grid (8 d-tiles, 32 row-tiles, 64 = bb + which*32), block 256 (32x8).
// ---------------------------------------------------------------------------
__global__ void __launch_bounds__(256) k_conv(const float* __restrict__ a,
                                              const float* __restrict__ b) {
    const int z     = blockIdx.z;
    const int which = z >> 5;               // 0: a, 1: b
    const int bb    = z & 31;
    const int dt    = blockIdx.x * 32;
    const int rt    = blockIdx.y * 32;
    const float* src = which ? b : a;
    const int* idx   = (which ? g_idxB : g_idxA) + bb * NL;
    __nv_bfloat16* oH  = which ? g_Bhi  : g_Ahi;
    __nv_bfloat16* oL  = which ? g_Blo  : g_Alo;
    __nv_bfloat16* oHT = which ? g_BhiT : g_AhiT;
    __nv_bfloat16* oLT = which ? g_BloT : g_AloT;

    const int tx = threadIdx.x & 31;
    const int ty = threadIdx.x >> 5;
    __shared__ float tile[32][33];

#pragma unroll
    for (int rr = 0; rr < 4; rr++) {
        int rl = ty + 8 * rr;
        int grow = idx[rt + rl];
        float v = src[((size_t)bb * NL + grow) * ND + dt + tx];
        tile[rl][tx] = v;
        __nv_bfloat16 h = __float2bfloat16(v);
        __nv_bfloat16 l = __float2bfloat16(v - __bfloat162float(h));
        size_t o = ((size_t)bb * NL + rt + rl) * ND + dt + tx;
        oH[o] = h; oL[o] = l;
    }
    __syncthreads();
#pragma unroll
    for (int rr = 0; rr < 4; rr++) {
        int dl = ty + 8 * rr;
        float v = tile[tx][dl];
        __nv_bfloat16 h = __float2bfloat16(v);
        __nv_bfloat16 l = __float2bfloat16(v - __bfloat162float(h));
        size_t o = ((size_t)bb * ND + dt + dl) * NL + rt + tx;
        oHT[o] = h; oLT[o] = l;
    }
}

// ---------------------------------------------------------------------------
// K1: S = a_c @ b_c^T (compact), 3-term bf16 mma.sync, writes g_S AND g_ST.
// CTA tile 128x128, K=256 in chunks of 32. 8 warps as 4(M)x2(N), warp 32x64.
// ---------------------------------------------------------------------------
__global__ void __launch_bounds__(256) k1_mma() {
    const int bb  = blockIdx.z;
    const int ib0 = blockIdx.y * 128;
    const int jb0 = blockIdx.x * 128;
    const int na  = g_cntA[bb];
    const int nb  = g_cntB[bb];
    if (ib0 >= na || jb0 >= nb) return;

    __shared__ __align__(16) char smem[4 * 128 * RS * 2];  // 40960B
    __nv_bfloat16* sAh = (__nv_bfloat16*)smem;
    __nv_bfloat16* sAl = sAh + 128 * RS;
    __nv_bfloat16* sBh = sAl + 128 * RS;
    __nv_bfloat16* sBl = sBh + 128 * RS;
    float* tbuf = (float*)smem;  // reused post-MMA

    const int t    = threadIdx.x;
    const int lane = t & 31;
    const int wid  = t >> 5;
    const int wm   = wid >> 1;   // 0..3
    const int wn   = wid & 1;    // 0..1
    const int gq   = lane >> 2;  // group row 0..7
    const int qk   = (lane & 3) * 2;

    float c[2][8][4];
#pragma unroll
    for (int mf = 0; mf < 2; mf++)
#pragma unroll
        for (int nf = 0; nf < 8; nf++)
#pragma unroll
            for (int v = 0; v < 4; v++) c[mf][nf][v] = 0.f;

    const size_t aBase = ((size_t)bb * NL + ib0) * ND;
    const size_t bBase = ((size_t)bb * NL + jb0) * ND;

#pragma unroll 1
    for (int kc = 0; kc < ND; kc += 32) {
        __syncthreads();
#pragma unroll
        for (int q = 0; q < 4; q++) {
            int id  = t + 256 * q;
            int row = id >> 3;
            int cc  = (id & 7) * 4;
            size_t go = (size_t)row * ND + kc + cc;
            int so = row * RS + cc;
            *(uint2*)&sAh[so] = *(const uint2*)&g_Ahi[aBase + go];
            *(uint2*)&sAl[so] = *(const uint2*)&g_Alo[aBase + go];
            *(uint2*)&sBh[so] = *(const uint2*)&g_Bhi[bBase + go];
            *(uint2*)&sBl[so] = *(const uint2*)&g_Blo[bBase + go];
        }
        __syncthreads();
#pragma unroll
        for (int term = 0; term < 3; term++) {
            const __nv_bfloat16* pA = (term == 2) ? sAl : sAh;
            const __nv_bfloat16* pB = (term == 1) ? sBl : sBh;
#pragma unroll
            for (int k0 = 0; k0 < 32; k0 += 16) {
                uint32_t B0[8], B1[8];
#pragma unroll
                for (int nf = 0; nf < 8; nf++) {
                    int n = wn * 64 + nf * 8 + gq;
                    B0[nf] = lds32(&pB[n * RS + k0 + qk]);
                    B1[nf] = lds32(&pB[n * RS + k0 + qk + 8]);
                }
#pragma unroll
                for (int mf = 0; mf < 2; mf++) {
                    int r = wm * 32 + mf * 16 + gq;
                    uint32_t a0 = lds32(&pA[r * RS + k0 + qk]);
                    uint32_t a1 = lds32(&pA[(r + 8) * RS + k0 + qk]);
                    uint32_t a2 = lds32(&pA[r * RS + k0 + qk + 8]);
                    uint32_t a3 = lds32(&pA[(r + 8) * RS + k0 + qk + 8]);
#pragma unroll
                    for (int nf = 0; nf < 8; nf++)
                        mma_bf16(c[mf][nf], a0, a1, a2, a3, B0[nf], B1[nf]);
                }
            }
        }
    }

    // ---- epilogue 1: direct store to g_S
#pragma unroll
    for (int mf = 0; mf < 2; mf++)
#pragma unroll
        for (int nf = 0; nf < 8; nf++) {
            int r  = ib0 + wm * 32 + mf * 16 + gq;
            int jj = jb0 + wn * 64 + nf * 8 + 2 * (lane & 3);
            *(float2*)&g_S[((size_t)(bb * NL) + r) * NL + jj] =
                make_float2(c[mf][nf][0], c[mf][nf][1]);
            *(float2*)&g_S[((size_t)(bb * NL) + r + 8) * NL + jj] =
                make_float2(c[mf][nf][2], c[mf][nf][3]);
        }

    // ---- epilogue 2: transpose to g_ST via smem, 4 passes of 32 j-cols
#pragma unroll 1
    for (int p = 0; p < 4; p++) {
        __syncthreads();
        if (wn == (p >> 1)) {
            int nfb = (p & 1) * 4;
#pragma unroll
            for (int mf = 0; mf < 2; mf++)
#pragma unroll
                for (int nfo = 0; nfo < 4; nfo++) {
                    int nf = nfb + nfo;
                    int jl = wn * 64 + nf * 8 + 2 * (lane & 3) - p * 32;
                    int il = wm * 32 + mf * 16 + gq;
                    tbuf[jl * 132 + il]           = c[mf][nf][0];
                    tbuf[(jl + 1) * 132 + il]     = c[mf][nf][1];
                    tbuf[jl * 132 + il + 8]       = c[mf][nf][2];
                    tbuf[(jl + 1) * 132 + il + 8] = c[mf][nf][3];
                }
        }
        __syncthreads();
#pragma unroll
        for (int q = 0; q < 4; q++) {
            int id  = t + 256 * q;
            int jl  = id >> 5;
            int il4 = (id & 31) * 4;
            int gj  = jb0 + p * 32 + jl;
            *(float4*)&g_ST[((size_t)(bb * NL) + gj) * NL + ib0 + il4] =
                *(float4*)&tbuf[jl * 132 + il4];
        }
    }
}

// ---------------------------------------------------------------------------
// K2: softmax stats, row-wise scans on g_S (which=0) or g_ST (which=1).
// 1 warp / compact row.
// ---------------------------------------------------------------------------
__global__ void __launch_bounds__(256) k2_stats(int which) {
    const int warp  = threadIdx.x >> 5;
    const int lane  = threadIdx.x & 31;
    const int rowid = blockIdx.x * 8 + warp;
    const int bb    = rowid >> 10;
    const int r     = rowid & (NL - 1);
    const int cntM  = which ? g_cntB[bb] : g_cntA[bb];
    const int cntK  = which ? g_cntA[bb] : g_cntB[bb];
    if (r >= cntM) return;
    const float* Srow = (which ? g_ST : g_S) + (size_t)rowid * NL;
    float* oMax = which ? g_colMax : g_rowMax;
    float* oSc  = which ? g_colScale : g_rowScale;

    const int k4 = cntK & ~3;
    float m = -INFINITY;
    for (int j = lane * 4; j < k4; j += 128) {
        float4 v = *(const float4*)(Srow + j);
        m = fmaxf(m, fmaxf(fmaxf(v.x, v.y), fmaxf(v.z, v.w)));
    }
    for (int j = k4 + lane; j < cntK; j += 32) m = fmaxf(m, Srow[j]);
#pragma unroll
    for (int o = 16; o > 0; o >>= 1) m = fmaxf(m, __shfl_xor_sync(0xffffffffu, m, o));

    float s = 0.f;
    if (m != -INFINITY) {
        for (int j = lane * 4; j < k4; j += 128) {
            float4 v = *(const float4*)(Srow + j);
            s += __expf(v.x - m) + __expf(v.y - m) + __expf(v.z - m) + __expf(v.w - m);
        }
        for (int j = k4 + lane; j < cntK; j += 32) s += __expf(Srow[j] - m);
    }
#pragma unroll
    for (int o = 16; o > 0; o >>= 1) s += __shfl_xor_sync(0xffffffffu, s, o);

    if (lane == 0) {
        if (m == -INFINITY) { oMax[rowid] = 0.f; oSc[rowid] = 0.f; }
        else                { oMax[rowid] = m;   oSc[rowid] = 1.f / s; }
    }
}

// ---------------------------------------------------------------------------
// K3: attended = softmax-weights @ values, 3-term bf16 mma.sync.
// which=0: out rows = idxA (M over compact i, K over compact j, V = b^T arrays)
// which=1: out rows = idxB (M over compact j, K over compact i, V = a^T arrays)
// CTA tile: M=128 x 128 d-cols; grid (2, 8, NB).
// ---------------------------------------------------------------------------
__global__ void __launch_bounds__(256) k3_mma(int which, float* __restrict__ out) {
    const int bb  = blockIdx.z;
    const int m0  = blockIdx.y * 128;
    const int db0 = blockIdx.x * 128;
    const int cntM = which ? g_cntB[bb] : g_cntA[bb];
    const int cntK = which ? g_cntA[bb] : g_cntB[bb];
    if (m0 >= cntM) return;

    const float* Sarr = which ? g_ST : g_S;
    const float* stM  = which ? g_colMax : g_rowMax;
    const float* stSc = which ? g_colScale : g_rowScale;
    const __nv_bfloat16* VhT = which ? g_AhiT : g_BhiT;
    const __nv_bfloat16* VlT = which ? g_AloT : g_BloT;
    const int* idxOut = (which ? g_idxB : g_idxA) + bb * NL;

    __shared__ __align__(16) char smem[4 * 128 * RS * 2];
    __nv_bfloat16* sWh = (__nv_bfloat16*)smem;
    __nv_bfloat16* sWl = sWh + 128 * RS;
    __nv_bfloat16* sVh = sWl + 128 * RS;
    __nv_bfloat16* sVl = sVh + 128 * RS;
    __shared__ float sM[128], sSc[128];
    __shared__ int   sIdx[128];

    const int t    = threadIdx.x;
    const int lane = t & 31;
    const int wid  = t >> 5;
    const int wm   = wid >> 1;
    const int wn   = wid & 1;
    const int gq   = lane >> 2;
    const int qk   = (lane & 3) * 2;

    if (t < 128) {
        sM[t]   = stM[bb * NL + m0 + t];
        sSc[t]  = stSc[bb * NL + m0 + t];
        sIdx[t] = idxOut[m0 + t];
    }

    float c[2][8][4];
#pragma unroll
    for (int mf = 0; mf < 2; mf++)
#pragma unroll
        for (int nf = 0; nf < 8; nf++)
#pragma unroll
            for (int v = 0; v < 4; v++) c[mf][nf][v] = 0.f;

    const size_t sBase = ((size_t)bb * NL + m0) * NL;
    const size_t vBase = ((size_t)bb * ND + db0) * NL;
    const int kend = (cntK + 31) & ~31;

#pragma unroll 1
    for (int kc = 0; kc < kend; kc += 32) {
        __syncthreads();
#pragma unroll
        for (int q = 0; q < 4; q++) {
            int id  = t + 256 * q;
            int row = id >> 3;
            int cc  = (id & 7) * 4;
            // W tile: exp(S - M) hi/lo
            float4 v = *(const float4*)&Sarr[sBase + (size_t)row * NL + kc + cc];
            float mr = sM[row];
            float w0 = (kc + cc + 0 < cntK) ? __expf(v.x - mr) : 0.f;
            float w1 = (kc + cc + 1 < cntK) ? __expf(v.y - mr) : 0.f;
            float w2 = (kc + cc + 2 < cntK) ? __expf(v.z - mr) : 0.f;
            float w3 = (kc + cc + 3 < cntK) ? __expf(v.w - mr) : 0.f;
            __nv_bfloat16 h0 = __float2bfloat16(w0), h1 = __float2bfloat16(w1);
            __nv_bfloat16 h2 = __float2bfloat16(w2), h3 = __float2bfloat16(w3);
            int so = row * RS + cc;
            sWh[so + 0] = h0; sWh[so + 1] = h1; sWh[so + 2] = h2; sWh[so + 3] = h3;
            sWl[so + 0] = __float2bfloat16(w0 - __bfloat162float(h0));
            sWl[so + 1] = __float2bfloat16(w1 - __bfloat162float(h1));
            sWl[so + 2] = __float2bfloat16(w2 - __bfloat162float(h2));
            sWl[so + 3] = __float2bfloat16(w3 - __bfloat162float(h3));
            // V tile (transposed arrays: rows = d, k contiguous)
            size_t go = vBase + (size_t)row * NL + kc + cc;
            *(uint2*)&sVh[so] = *(const uint2*)&VhT[go];
            *(uint2*)&sVl[so] = *(const uint2*)&VlT[go];
        }
        __syncthreads();
#pragma unroll
        for (int term = 0; term < 3; term++) {
            const __nv_bfloat16* pA = (term == 2) ? sWl : sWh;
            const __nv_bfloat16* pB = (term == 1) ? sVl : sVh;
#pragma unroll
            for (int k0 = 0; k0 < 32; k0 += 16) {
                uint32_t B0[8], B1[8];
#pragma unroll
                for (int nf = 0; nf < 8; nf++) {
                    int n = wn * 64 + nf * 8 + gq;
                    B0[nf] = lds32(&pB[n * RS + k0 + qk]);
                    B1[nf] = lds32(&pB[n * RS + k0 + qk + 8]);
                }
#pragma unroll
                for (int mf = 0; mf < 2; mf++) {
                    int r = wm * 32 + mf * 16 + gq;
                    uint32_t a0 = lds32(&pA[r * RS + k0 + qk]);
                    uint32_t a1 = lds32(&pA[(r + 8) * RS + k0 + qk]);
                    uint32_t a2 = lds32(&pA[r * RS + k0 + qk + 8]);
                    uint32_t a3 = lds32(&pA[(r + 8) * RS + k0 + qk + 8]);
#pragma unroll
                    for (int nf = 0; nf < 8; nf++)
                        mma_bf16(c[mf][nf], a0, a1, a2, a3, B0[nf], B1[nf]);
                }
            }
        }
    }

    // ---- epilogue: scale + scatter
#pragma unroll
    for (int mf = 0; mf < 2; mf++) {
        int rl = wm * 32 + mf * 16 + gq;
#pragma unroll
        for (int nf = 0; nf < 8; nf++) {
            int jj = db0 + wn * 64 + nf * 8 + 2 * (lane & 3);
            if (m0 + rl < cntM) {
                float sc = sSc[rl];
                *(float2*)&out[((size_t)(bb * NL) + sIdx[rl]) * ND + jj] =
                    make_float2(c[mf][nf][0] * sc, c[mf][nf][1] * sc);
            }
            if (m0 + rl + 8 < cntM) {
                float sc = sSc[rl + 8];
                *(float2*)&out[((size_t)(bb * NL) + sIdx[rl + 8]) * ND + jj] =
                    make_float2(c[mf][nf][2] * sc, c[mf][nf][3] * sc);
            }
        }
    }
}

// ---------------------------------------------------------------------------
extern "C" void kernel_launch(void* const* d_in, const int* in_sizes, int n_in,
                              void* d_out, int out_size) {
    const float* a      = (const float*)d_in[0];
    const float* b      = (const float*)d_in[1];
    const int*   mask_a = (const int*)d_in[2];
    const int*   mask_b = (const int*)d_in[3];
    float* outA = (float*)d_out;
    float* outB = outA + (size_t)NB * NL * ND;

    cudaMemsetAsync(d_out, 0, (size_t)out_size * sizeof(float));

    k0_compact<<<64, 1024>>>(mask_a, mask_b);
    k_conv<<<dim3(8, 32, 64), 256>>>(a, b);
    k1_mma<<<dim3(8, 8, NB), 256>>>();
    k2_stats<<<NB * NL / 8, 256>>>(0);
    k2_stats<<<NB * NL / 8, 256>>>(1);
    k3_mma<<<dim3(2, 8, NB), 256>>>(0, outA);
    k3_mma<<<dim3(2, 8, NB), 256>>>(1, outB);
}

// round 5
// speedup vs baseline: 4.4254x; 1.3533x over previous
#include <cuda_runtime.h>
#include <cuda_bf16.h>
#include <math.h>
#include <cstdint>

// Problem constants
constexpr int NB = 32;    // batch
constexpr int NL = 1024;  // La = Lb
constexpr int ND = 256;   // feature dim

// Scratch
__device__ float g_S [(size_t)NB * NL * NL];   // logits, compact [i][j]
__device__ float g_ST[(size_t)NB * NL * NL];   // logits transposed, compact [j][i]
__device__ float g_rowMax[NB * NL];
__device__ float g_rowScale[NB * NL];
__device__ float g_colMax[NB * NL];
__device__ float g_colScale[NB * NL];
__device__ int   g_idxA[NB * NL];
__device__ int   g_idxB[NB * NL];
__device__ int   g_cntA[NB];
__device__ int   g_cntB[NB];

// Compacted bf16 hi/lo copies of a, b (row = compact position), plus transposed.
__device__ __nv_bfloat16 g_Ahi [(size_t)NB * NL * ND];
__device__ __nv_bfloat16 g_Alo [(size_t)NB * NL * ND];
__device__ __nv_bfloat16 g_Bhi [(size_t)NB * NL * ND];
__device__ __nv_bfloat16 g_Blo [(size_t)NB * NL * ND];
__device__ __nv_bfloat16 g_AhiT[(size_t)NB * ND * NL];   // [d][i_compact]
__device__ __nv_bfloat16 g_AloT[(size_t)NB * ND * NL];
__device__ __nv_bfloat16 g_BhiT[(size_t)NB * ND * NL];   // [d][j_compact]
__device__ __nv_bfloat16 g_BloT[(size_t)NB * ND * NL];

constexpr int RS = 40;  // smem bf16 row stride (32 data + 8 pad); 80B rows -> LDSM conflict-free

// m16n8k16 bf16 MMA, fp32 accumulate
__device__ __forceinline__ void mma_bf16(float* c, uint32_t a0, uint32_t a1,
                                         uint32_t a2, uint32_t a3,
                                         uint32_t b0, uint32_t b1) {
    asm volatile(
        "mma.sync.aligned.m16n8k16.row.col.f32.bf16.bf16.f32 "
        "{%0,%1,%2,%3}, {%4,%5,%6,%7}, {%8,%9}, {%0,%1,%2,%3};"
        : "+f"(c[0]), "+f"(c[1]), "+f"(c[2]), "+f"(c[3])
        : "r"(a0), "r"(a1), "r"(a2), "r"(a3), "r"(b0), "r"(b1));
}

__device__ __forceinline__ void ldsm_x4(uint32_t& r0, uint32_t& r1,
                                        uint32_t& r2, uint32_t& r3, uint32_t addr) {
    asm volatile("ldmatrix.sync.aligned.m8n8.x4.shared.b16 {%0,%1,%2,%3}, [%4];"
        : "=r"(r0), "=r"(r1), "=r"(r2), "=r"(r3) : "r"(addr));
}

__device__ __forceinline__ uint32_t smem_u32(const void* p) {
    uint32_t a;
    asm("{ .reg .u64 tmp; cvta.to.shared.u64 tmp, %1; cvt.u32.u64 %0, tmp; }"
        : "=r"(a) : "l"(p));
    return a;
}

// ---------------------------------------------------------------------------
// K0: per-batch mask compaction (idx padded to 1024 with last valid index).
// ---------------------------------------------------------------------------
__global__ void __launch_bounds__(1024) k0_compact(const int* __restrict__ mask_a,
                                                   const int* __restrict__ mask_b) {
    const int which = blockIdx.x >> 5;
    const int bb    = blockIdx.x & 31;
    const int* m = (which ? mask_b : mask_a) + bb * NL;
    int* idx = (which ? g_idxB : g_idxA) + bb * NL;
    int* cnt = which ? g_cntB : g_cntA;
    const int t = threadIdx.x, lane = t & 31, w = t >> 5;

    int mv = (m[t] != 0);
    unsigned bal = __ballot_sync(0xffffffffu, mv);
    int pw = __popc(bal & ((1u << lane) - 1));
    __shared__ int wc[32];
    if (lane == 0) wc[w] = __popc(bal);
    __syncthreads();
    if (t < 32) {
        int v = wc[t];
#pragma unroll
        for (int o = 1; o < 32; o <<= 1) {
            int u = __shfl_up_sync(0xffffffffu, v, o);
            if (lane >= o) v += u;
        }
        wc[t] = v;
    }
    __syncthreads();
    const int base  = (w == 0) ? 0 : wc[w - 1];
    const int total = wc[31];
    if (mv) idx[base + pw] = t;
    if (t == 0) cnt[bb] = total;
    __syncthreads();
    __shared__ int lastIdx;
    if (t == 0) lastIdx = (total > 0) ? idx[total - 1] : 0;
    __syncthreads();
    if (t >= total) idx[t] = lastIdx;
}

// ---------------------------------------------------------------------------
// KC: gather-compact + fp32->bf16 hi/lo split + transpose.
// ---------------------------------------------------------------------------
__global__ void __launch_bounds__(256) k_conv(const float* __restrict__ a,
                                              const float* __restrict__ b) {
    const int z     = blockIdx.z;
    const int which = z >> 5;               // 0: a, 1: b
    const int bb    = z & 31;
    const int dt    = blockIdx.x * 32;
    const int rt    = blockIdx.y * 32;
    const float* src = which ? b : a;
    const int* idx   = (which ? g_idxB : g_idxA) + bb * NL;
    __nv_bfloat16* oH  = which ? g_Bhi  : g_Ahi;
    __nv_bfloat16* oL  = which ? g_Blo  : g_Alo;
    __nv_bfloat16* oHT = which ? g_BhiT : g_AhiT;
    __nv_bfloat16* oLT = which ? g_BloT : g_AloT;

    const int tx = threadIdx.x & 31;
    const int ty = threadIdx.x >> 5;
    __shared__ float tile[32][33];

#pragma unroll
    for (int rr = 0; rr < 4; rr++) {
        int rl = ty + 8 * rr;
        int grow = idx[rt + rl];
        float v = src[((size_t)bb * NL + grow) * ND + dt + tx];
        tile[rl][tx] = v;
        __nv_bfloat16 h = __float2bfloat16(v);
        __nv_bfloat16 l = __float2bfloat16(v - __bfloat162float(h));
        size_t o = ((size_t)bb * NL + rt + rl) * ND + dt + tx;
        oH[o] = h; oL[o] = l;
    }
    __syncthreads();
#pragma unroll
    for (int rr = 0; rr < 4; rr++) {
        int dl = ty + 8 * rr;
        float v = tile[tx][dl];
        __nv_bfloat16 h = __float2bfloat16(v);
        __nv_bfloat16 l = __float2bfloat16(v - __bfloat162float(h));
        size_t o = ((size_t)bb * ND + dt + dl) * NL + rt + tx;
        oHT[o] = h; oLT[o] = l;
    }
}

// ---------------------------------------------------------------------------
// K1: S = a_c @ b_c^T (compact), 3-term bf16 mma.sync with ldmatrix +
// register-pipelined global prefetch. Writes g_S AND g_ST.
// ---------------------------------------------------------------------------
__global__ void __launch_bounds__(256) k1_mma() {
    const int bb  = blockIdx.z;
    const int ib0 = blockIdx.y * 128;
    const int jb0 = blockIdx.x * 128;
    const int na  = g_cntA[bb];
    const int nb  = g_cntB[bb];
    if (ib0 >= na || jb0 >= nb) return;

    __shared__ __align__(16) __nv_bfloat16 sm[4 * 128 * RS];  // 40960B
    __nv_bfloat16* sAh = sm;
    __nv_bfloat16* sAl = sAh + 128 * RS;
    __nv_bfloat16* sBh = sAl + 128 * RS;
    __nv_bfloat16* sBl = sBh + 128 * RS;
    float* tbuf = (float*)sm;  // reused post-MMA

    const int t    = threadIdx.x;
    const int lane = t & 31;
    const int wid  = t >> 5;
    const int wm   = wid >> 1;   // 0..3
    const int wn   = wid & 1;    // 0..1
    const int gq   = lane >> 2;

    // ldmatrix lane offsets: row within 16-row block, col half-select
    const int lrow = (lane & 7) + ((lane >> 3) & 1) * 8;
    const int lcol = (lane >> 4) * 8;

    const uint32_t sAh_u = smem_u32(sAh), sAl_u = smem_u32(sAl);
    const uint32_t sBh_u = smem_u32(sBh), sBl_u = smem_u32(sBl);

    float c[2][8][4];
#pragma unroll
    for (int mf = 0; mf < 2; mf++)
#pragma unroll
        for (int nf = 0; nf < 8; nf++)
#pragma unroll
            for (int v = 0; v < 4; v++) c[mf][nf][v] = 0.f;

    const size_t aBase = ((size_t)bb * NL + ib0) * ND;
    const size_t bBase = ((size_t)bb * NL + jb0) * ND;
    const int lr0 = t >> 3;          // global-load base row (+32 per q)
    const int lc0 = (t & 7) * 4;     // global-load col within chunk

    uint2 rAh[4], rAl[4], rBh[4], rBl[4];
    // prefetch chunk 0
#pragma unroll
    for (int q = 0; q < 4; q++) {
        size_t go = (size_t)(lr0 + 32 * q) * ND + lc0;
        rAh[q] = *(const uint2*)&g_Ahi[aBase + go];
        rAl[q] = *(const uint2*)&g_Alo[aBase + go];
        rBh[q] = *(const uint2*)&g_Bhi[bBase + go];
        rBl[q] = *(const uint2*)&g_Blo[bBase + go];
    }

#pragma unroll 1
    for (int kc = 0; kc < ND; kc += 32) {
        // store staged chunk to smem
#pragma unroll
        for (int q = 0; q < 4; q++) {
            int so = (lr0 + 32 * q) * RS + lc0;
            *(uint2*)&sAh[so] = rAh[q];
            *(uint2*)&sAl[so] = rAl[q];
            *(uint2*)&sBh[so] = rBh[q];
            *(uint2*)&sBl[so] = rBl[q];
        }
        __syncthreads();
        // prefetch next chunk (overlaps with MMA below)
        if (kc + 32 < ND) {
#pragma unroll
            for (int q = 0; q < 4; q++) {
                size_t go = (size_t)(lr0 + 32 * q) * ND + kc + 32 + lc0;
                rAh[q] = *(const uint2*)&g_Ahi[aBase + go];
                rAl[q] = *(const uint2*)&g_Alo[aBase + go];
                rBh[q] = *(const uint2*)&g_Bhi[bBase + go];
                rBl[q] = *(const uint2*)&g_Blo[bBase + go];
            }
        }
#pragma unroll
        for (int term = 0; term < 3; term++) {
            const uint32_t au = (term == 2) ? sAl_u : sAh_u;
            const uint32_t bu = (term == 1) ? sBl_u : sBh_u;
#pragma unroll
            for (int k0 = 0; k0 < 32; k0 += 16) {
                uint32_t b0[8], b1[8];
#pragma unroll
                for (int nfp = 0; nfp < 4; nfp++) {
                    uint32_t addr = bu +
                        (uint32_t)(((wn * 64 + nfp * 16 + lrow) * RS + k0 + lcol) * 2);
                    ldsm_x4(b0[2 * nfp], b0[2 * nfp + 1], b1[2 * nfp], b1[2 * nfp + 1], addr);
                }
#pragma unroll
                for (int mf = 0; mf < 2; mf++) {
                    uint32_t a0, a1, a2, a3;
                    uint32_t addrA = au +
                        (uint32_t)(((wm * 32 + mf * 16 + lrow) * RS + k0 + lcol) * 2);
                    ldsm_x4(a0, a1, a2, a3, addrA);
#pragma unroll
                    for (int nf = 0; nf < 8; nf++)
                        mma_bf16(c[mf][nf], a0, a1, a2, a3, b0[nf], b1[nf]);
                }
            }
        }
        __syncthreads();
    }

    // ---- epilogue 1: direct store to g_S
#pragma unroll
    for (int mf = 0; mf < 2; mf++)
#pragma unroll
        for (int nf = 0; nf < 8; nf++) {
            int r  = ib0 + wm * 32 + mf * 16 + gq;
            int jj = jb0 + wn * 64 + nf * 8 + 2 * (lane & 3);
            *(float2*)&g_S[((size_t)(bb * NL) + r) * NL + jj] =
                make_float2(c[mf][nf][0], c[mf][nf][1]);
            *(float2*)&g_S[((size_t)(bb * NL) + r + 8) * NL + jj] =
                make_float2(c[mf][nf][2], c[mf][nf][3]);
        }

    // ---- epilogue 2: transpose to g_ST via smem, 4 passes of 32 j-cols
#pragma unroll 1
    for (int p = 0; p < 4; p++) {
        __syncthreads();
        if (wn == (p >> 1)) {
            int nfb = (p & 1) * 4;
#pragma unroll
            for (int mf = 0; mf < 2; mf++)
#pragma unroll
                for (int nfo = 0; nfo < 4; nfo++) {
                    int nf = nfb + nfo;
                    int jl = wn * 64 + nf * 8 + 2 * (lane & 3) - p * 32;
                    int il = wm * 32 + mf * 16 + gq;
                    tbuf[jl * 132 + il]           = c[mf][nf][0];
                    tbuf[(jl + 1) * 132 + il]     = c[mf][nf][1];
                    tbuf[jl * 132 + il + 8]       = c[mf][nf][2];
                    tbuf[(jl + 1) * 132 + il + 8] = c[mf][nf][3];
                }
        }
        __syncthreads();
#pragma unroll
        for (int q = 0; q < 4; q++) {
            int id  = t + 256 * q;
            int jl  = id >> 5;
            int il4 = (id & 31) * 4;
            int gj  = jb0 + p * 32 + jl;
            *(float4*)&g_ST[((size_t)(bb * NL) + gj) * NL + ib0 + il4] =
                *(float4*)&tbuf[jl * 132 + il4];
        }
    }
}

// ---------------------------------------------------------------------------
// K2: softmax stats, row-wise scans on g_S (which=0) or g_ST (which=1).
// ---------------------------------------------------------------------------
__global__ void __launch_bounds__(256) k2_stats(int which) {
    const int warp  = threadIdx.x >> 5;
    const int lane  = threadIdx.x & 31;
    const int rowid = blockIdx.x * 8 + warp;
    const int bb    = rowid >> 10;
    const int r     = rowid & (NL - 1);
    const int cntM  = which ? g_cntB[bb] : g_cntA[bb];
    const int cntK  = which ? g_cntA[bb] : g_cntB[bb];
    if (r >= cntM) return;
    const float* Srow = (which ? g_ST : g_S) + (size_t)rowid * NL;
    float* oMax = which ? g_colMax : g_rowMax;
    float* oSc  = which ? g_colScale : g_rowScale;

    const int k4 = cntK & ~3;
    float m = -INFINITY;
    for (int j = lane * 4; j < k4; j += 128) {
        float4 v = *(const float4*)(Srow + j);
        m = fmaxf(m, fmaxf(fmaxf(v.x, v.y), fmaxf(v.z, v.w)));
    }
    for (int j = k4 + lane; j < cntK; j += 32) m = fmaxf(m, Srow[j]);
#pragma unroll
    for (int o = 16; o > 0; o >>= 1) m = fmaxf(m, __shfl_xor_sync(0xffffffffu, m, o));

    float s = 0.f;
    if (m != -INFINITY) {
        for (int j = lane * 4; j < k4; j += 128) {
            float4 v = *(const float4*)(Srow + j);
            s += __expf(v.x - m) + __expf(v.y - m) + __expf(v.z - m) + __expf(v.w - m);
        }
        for (int j = k4 + lane; j < cntK; j += 32) s += __expf(Srow[j] - m);
    }
#pragma unroll
    for (int o = 16; o > 0; o >>= 1) s += __shfl_xor_sync(0xffffffffu, s, o);

    if (lane == 0) {
        if (m == -INFINITY) { oMax[rowid] = 0.f; oSc[rowid] = 0.f; }
        else                { oMax[rowid] = m;   oSc[rowid] = 1.f / s; }
    }
}

// ---------------------------------------------------------------------------
// K3: attended = softmax-weights @ values, 3-term bf16 mma.sync,
// ldmatrix fragments + register-pipelined global prefetch.
// ---------------------------------------------------------------------------
__global__ void __launch_bounds__(256) k3_mma(int which, float* __restrict__ out) {
    const int bb  = blockIdx.z;
    const int m0  = blockIdx.y * 128;
    const int db0 = blockIdx.x * 128;
    const int cntM = which ? g_cntB[bb] : g_cntA[bb];
    const int cntK = which ? g_cntA[bb] : g_cntB[bb];
    if (m0 >= cntM) return;

    const float* Sarr = which ? g_ST : g_S;
    const float* stM  = which ? g_colMax : g_rowMax;
    const float* stSc = which ? g_colScale : g_rowScale;
    const __nv_bfloat16* VhT = which ? g_AhiT : g_BhiT;
    const __nv_bfloat16* VlT = which ? g_AloT : g_BloT;
    const int* idxOut = (which ? g_idxB : g_idxA) + bb * NL;

    __shared__ __align__(16) __nv_bfloat16 smh[4 * 128 * RS];
    __nv_bfloat16* sWh = smh;
    __nv_bfloat16* sWl = sWh + 128 * RS;
    __nv_bfloat16* sVh = sWl + 128 * RS;
    __nv_bfloat16* sVl = sVh + 128 * RS;
    __shared__ float sM[128], sSc[128];
    __shared__ int   sIdx[128];

    const int t    = threadIdx.x;
    const int lane = t & 31;
    const int wid  = t >> 5;
    const int wm   = wid >> 1;
    const int wn   = wid & 1;
    const int gq   = lane >> 2;

    const int lrow = (lane & 7) + ((lane >> 3) & 1) * 8;
    const int lcol = (lane >> 4) * 8;

    const uint32_t sWh_u = smem_u32(sWh), sWl_u = smem_u32(sWl);
    const uint32_t sVh_u = smem_u32(sVh), sVl_u = smem_u32(sVl);

    if (t < 128) {
        sM[t]   = stM[bb * NL + m0 + t];
        sSc[t]  = stSc[bb * NL + m0 + t];
        sIdx[t] = idxOut[m0 + t];
    }
    __syncthreads();

    float c[2][8][4];
#pragma unroll
    for (int mf = 0; mf < 2; mf++)
#pragma unroll
        for (int nf = 0; nf < 8; nf++)
#pragma unroll
            for (int v = 0; v < 4; v++) c[mf][nf][v] = 0.f;

    const size_t sBase = ((size_t)bb * NL + m0) * NL;
    const size_t vBase = ((size_t)bb * ND + db0) * NL;
    const int kend = (cntK + 31) & ~31;
    const int lr0 = t >> 3;
    const int lc0 = (t & 7) * 4;

    float4 rS[4];
    uint2 rVh[4], rVl[4];
    // prefetch chunk 0
#pragma unroll
    for (int q = 0; q < 4; q++) {
        int row = lr0 + 32 * q;
        rS[q]  = *(const float4*)&Sarr[sBase + (size_t)row * NL + lc0];
        rVh[q] = *(const uint2*)&VhT[vBase + (size_t)row * NL + lc0];
        rVl[q] = *(const uint2*)&VlT[vBase + (size_t)row * NL + lc0];
    }

#pragma unroll 1
    for (int kc = 0; kc < kend; kc += 32) {
        // store staged chunk: W = split(exp(S - M)), V raw
        const float mr = sM[lr0];  // same row for all q? no: row varies by q
#pragma unroll
        for (int q = 0; q < 4; q++) {
            int row = lr0 + 32 * q;
            float mrq = sM[row];
            float w0 = (kc + lc0 + 0 < cntK) ? __expf(rS[q].x - mrq) : 0.f;
            float w1 = (kc + lc0 + 1 < cntK) ? __expf(rS[q].y - mrq) : 0.f;
            float w2 = (kc + lc0 + 2 < cntK) ? __expf(rS[q].z - mrq) : 0.f;
            float w3 = (kc + lc0 + 3 < cntK) ? __expf(rS[q].w - mrq) : 0.f;
            __nv_bfloat16 h0 = __float2bfloat16(w0), h1 = __float2bfloat16(w1);
            __nv_bfloat16 h2 = __float2bfloat16(w2), h3 = __float2bfloat16(w3);
            int so = row * RS + lc0;
            sWh[so + 0] = h0; sWh[so + 1] = h1; sWh[so + 2] = h2; sWh[so + 3] = h3;
            sWl[so + 0] = __float2bfloat16(w0 - __bfloat162float(h0));
            sWl[so + 1] = __float2bfloat16(w1 - __bfloat162float(h1));
            sWl[so + 2] = __float2bfloat16(w2 - __bfloat162float(h2));
            sWl[so + 3] = __float2bfloat16(w3 - __bfloat162float(h3));
            *(uint2*)&sVh[so] = rVh[q];
            *(uint2*)&sVl[so] = rVl[q];
        }
        (void)mr;
        __syncthreads();
        // prefetch next chunk
        if (kc + 32 < kend) {
#pragma unroll
            for (int q = 0; q < 4; q++) {
                int row = lr0 + 32 * q;
                rS[q]  = *(const float4*)&Sarr[sBase + (size_t)row * NL + kc + 32 + lc0];
                rVh[q] = *(const uint2*)&VhT[vBase + (size_t)row * NL + kc + 32 + lc0];
                rVl[q] = *(const uint2*)&VlT[vBase + (size_t)row * NL + kc + 32 + lc0];
            }
        }
#pragma unroll
        for (int term = 0; term < 3; term++) {
            const uint32_t au = (term == 2) ? sWl_u : sWh_u;
            const uint32_t bu = (term == 1) ? sVl_u : sVh_u;
#pragma unroll
            for (int k0 = 0; k0 < 32; k0 += 16) {
                uint32_t b0[8], b1[8];
#pragma unroll
                for (int nfp = 0; nfp < 4; nfp++) {
                    uint32_t addr = bu +
                        (uint32_t)(((wn * 64 + nfp * 16 + lrow) * RS + k0 + lcol) * 2);
                    ldsm_x4(b0[2 * nfp], b0[2 * nfp + 1], b1[2 * nfp], b1[2 * nfp + 1], addr);
                }
#pragma unroll
                for (int mf = 0; mf < 2; mf++) {
                    uint32_t a0, a1, a2, a3;
                    uint32_t addrA = au +
                        (uint32_t)(((wm * 32 + mf * 16 + lrow) * RS + k0 + lcol) * 2);
                    ldsm_x4(a0, a1, a2, a3, addrA);
#pragma unroll
                    for (int nf = 0; nf < 8; nf++)
                        mma_bf16(c[mf][nf], a0, a1, a2, a3, b0[nf], b1[nf]);
                }
            }
        }
        __syncthreads();
    }

    // ---- epilogue: scale + scatter
#pragma unroll
    for (int mf = 0; mf < 2; mf++) {
        int rl = wm * 32 + mf * 16 + gq;
#pragma unroll
        for (int nf = 0; nf < 8; nf++) {
            int jj = db0 + wn * 64 + nf * 8 + 2 * (lane & 3);
            if (m0 + rl < cntM) {
                float sc = sSc[rl];
                *(float2*)&out[((size_t)(bb * NL) + sIdx[rl]) * ND + jj] =
                    make_float2(c[mf][nf][0] * sc, c[mf][nf][1] * sc);
            }
            if (m0 + rl + 8 < cntM) {
                float sc = sSc[rl + 8];
                *(float2*)&out[((size_t)(bb * NL) + sIdx[rl + 8]) * ND + jj] =
                    make_float2(c[mf][nf][2] * sc, c[mf][nf][3] * sc);
            }
        }
    }
}

// ---------------------------------------------------------------------------
extern "C" void kernel_launch(void* const* d_in, const int* in_sizes, int n_in,
                              void* d_out, int out_size) {
    const float* a      = (const float*)d_in[0];
    const float* b      = (const float*)d_in[1];
    const int*   mask_a = (const int*)d_in[2];
    const int*   mask_b = (const int*)d_in[3];
    float* outA = (float*)d_out;
    float* outB = outA + (size_t)NB * NL * ND;

    cudaMemsetAsync(d_out, 0, (size_t)out_size * sizeof(float));

    k0_compact<<<64, 1024>>>(mask_a, mask_b);
    k_conv<<<dim3(8, 32, 64), 256>>>(a, b);
    k1_mma<<<dim3(8, 8, NB), 256>>>();
    k2_stats<<<NB * NL / 8, 256>>>(0);
    k2_stats<<<NB * NL / 8, 256>>>(1);
    k3_mma<<<dim3(2, 8, NB), 256>>>(0, outA);
    k3_mma<<<dim3(2, 8, NB), 256>>>(1, outB);
}

// round 6
// speedup vs baseline: 4.9116x; 1.1099x over previous
#include <cuda_runtime.h>
#include <cuda_bf16.h>
#include <math.h>
#include <cstdint>

// Problem constants
constexpr int NB = 32;    // batch
constexpr int NL = 1024;  // La = Lb
constexpr int ND = 256;   // feature dim

// Scratch
__device__ float g_S [(size_t)NB * NL * NL];   // logits, compact [i][j]
__device__ float g_ST[(size_t)NB * NL * NL];   // logits transposed, compact [j][i]
__device__ float g_rowMax[NB * NL];
__device__ float g_rowScale[NB * NL];
__device__ float g_colMax[NB * NL];
__device__ float g_colScale[NB * NL];
__device__ int   g_idxA[NB * NL];
__device__ int   g_idxB[NB * NL];
__device__ int   g_cntA[NB];
__device__ int   g_cntB[NB];

// Compacted bf16 hi/lo copies of a, b (row = compact position), plus transposed.
__device__ __nv_bfloat16 g_Ahi [(size_t)NB * NL * ND];
__device__ __nv_bfloat16 g_Alo [(size_t)NB * NL * ND];
__device__ __nv_bfloat16 g_Bhi [(size_t)NB * NL * ND];
__device__ __nv_bfloat16 g_Blo [(size_t)NB * NL * ND];
__device__ __nv_bfloat16 g_AhiT[(size_t)NB * ND * NL];   // [d][i_compact]
__device__ __nv_bfloat16 g_AloT[(size_t)NB * ND * NL];
__device__ __nv_bfloat16 g_BhiT[(size_t)NB * ND * NL];   // [d][j_compact]
__device__ __nv_bfloat16 g_BloT[(size_t)NB * ND * NL];

constexpr int RS = 40;  // smem bf16 row stride (32 data + 8 pad); 80B rows -> LDSM conflict-free

// m16n8k16 bf16 MMA, fp32 accumulate
__device__ __forceinline__ void mma_bf16(float* c, uint32_t a0, uint32_t a1,
                                         uint32_t a2, uint32_t a3,
                                         uint32_t b0, uint32_t b1) {
    asm volatile(
        "mma.sync.aligned.m16n8k16.row.col.f32.bf16.bf16.f32 "
        "{%0,%1,%2,%3}, {%4,%5,%6,%7}, {%8,%9}, {%0,%1,%2,%3};"
        : "+f"(c[0]), "+f"(c[1]), "+f"(c[2]), "+f"(c[3])
        : "r"(a0), "r"(a1), "r"(a2), "r"(a3), "r"(b0), "r"(b1));
}

__device__ __forceinline__ void ldsm_x4(uint32_t& r0, uint32_t& r1,
                                        uint32_t& r2, uint32_t& r3, uint32_t addr) {
    asm volatile("ldmatrix.sync.aligned.m8n8.x4.shared.b16 {%0,%1,%2,%3}, [%4];"
        : "=r"(r0), "=r"(r1), "=r"(r2), "=r"(r3) : "r"(addr));
}

__device__ __forceinline__ uint32_t smem_u32(const void* p) {
    uint32_t a;
    asm("{ .reg .u64 tmp; cvta.to.shared.u64 tmp, %1; cvt.u32.u64 %0, tmp; }"
        : "=r"(a) : "l"(p));
    return a;
}

__device__ __forceinline__ void cpasync16(uint32_t saddr, const void* gptr) {
    asm volatile("cp.async.cg.shared.global [%0], [%1], 16;"
        :: "r"(saddr), "l"(gptr) : "memory");
}
__device__ __forceinline__ void cpasync_commit() {
    asm volatile("cp.async.commit_group;" ::: "memory");
}
__device__ __forceinline__ void cpasync_wait0() {
    asm volatile("cp.async.wait_group 0;" ::: "memory");
}

// ---------------------------------------------------------------------------
// K0: per-batch mask compaction (idx padded to 1024 with last valid index).
// ---------------------------------------------------------------------------
__global__ void __launch_bounds__(1024) k0_compact(const int* __restrict__ mask_a,
                                                   const int* __restrict__ mask_b) {
    const int which = blockIdx.x >> 5;
    const int bb    = blockIdx.x & 31;
    const int* m = (which ? mask_b : mask_a) + bb * NL;
    int* idx = (which ? g_idxB : g_idxA) + bb * NL;
    int* cnt = which ? g_cntB : g_cntA;
    const int t = threadIdx.x, lane = t & 31, w = t >> 5;

    int mv = (m[t] != 0);
    unsigned bal = __ballot_sync(0xffffffffu, mv);
    int pw = __popc(bal & ((1u << lane) - 1));
    __shared__ int wc[32];
    if (lane == 0) wc[w] = __popc(bal);
    __syncthreads();
    if (t < 32) {
        int v = wc[t];
#pragma unroll
        for (int o = 1; o < 32; o <<= 1) {
            int u = __shfl_up_sync(0xffffffffu, v, o);
            if (lane >= o) v += u;
        }
        wc[t] = v;
    }
    __syncthreads();
    const int base  = (w == 0) ? 0 : wc[w - 1];
    const int total = wc[31];
    if (mv) idx[base + pw] = t;
    if (t == 0) cnt[bb] = total;
    __syncthreads();
    __shared__ int lastIdx;
    if (t == 0) lastIdx = (total > 0) ? idx[total - 1] : 0;
    __syncthreads();
    if (t >= total) idx[t] = lastIdx;
}

// ---------------------------------------------------------------------------
// KC: gather-compact + fp32->bf16 hi/lo split + transpose.
// Early-exits row-tiles beyond roundup(cnt,128) (never read downstream).
// ---------------------------------------------------------------------------
__global__ void __launch_bounds__(256) k_conv(const float* __restrict__ a,
                                              const float* __restrict__ b) {
    const int z     = blockIdx.z;
    const int which = z >> 5;               // 0: a, 1: b
    const int bb    = z & 31;
    const int dt    = blockIdx.x * 32;
    const int rt    = blockIdx.y * 32;
    const int cnt   = which ? g_cntB[bb] : g_cntA[bb];
    if (rt >= ((cnt + 127) & ~127)) return;
    const float* src = which ? b : a;
    const int* idx   = (which ? g_idxB : g_idxA) + bb * NL;
    __nv_bfloat16* oH  = which ? g_Bhi  : g_Ahi;
    __nv_bfloat16* oL  = which ? g_Blo  : g_Alo;
    __nv_bfloat16* oHT = which ? g_BhiT : g_AhiT;
    __nv_bfloat16* oLT = which ? g_BloT : g_AloT;

    const int tx = threadIdx.x & 31;
    const int ty = threadIdx.x >> 5;
    __shared__ float tile[32][33];

#pragma unroll
    for (int rr = 0; rr < 4; rr++) {
        int rl = ty + 8 * rr;
        int grow = idx[rt + rl];
        float v = src[((size_t)bb * NL + grow) * ND + dt + tx];
        tile[rl][tx] = v;
        __nv_bfloat16 h = __float2bfloat16(v);
        __nv_bfloat16 l = __float2bfloat16(v - __bfloat162float(h));
        size_t o = ((size_t)bb * NL + rt + rl) * ND + dt + tx;
        oH[o] = h; oL[o] = l;
    }
    __syncthreads();
#pragma unroll
    for (int rr = 0; rr < 4; rr++) {
        int dl = ty + 8 * rr;
        float v = tile[tx][dl];
        __nv_bfloat16 h = __float2bfloat16(v);
        __nv_bfloat16 l = __float2bfloat16(v - __bfloat162float(h));
        size_t o = ((size_t)bb * ND + dt + dl) * NL + rt + tx;
        oHT[o] = h; oLT[o] = l;
    }
}

// ---------------------------------------------------------------------------
// K1: S = a_c @ b_c^T (compact), 3-term bf16 mma.sync with ldmatrix +
// cp.async staged loads (low reg pressure, 2 CTAs/SM). Writes g_S AND g_ST.
// ---------------------------------------------------------------------------
__global__ void __launch_bounds__(256, 2) k1_mma() {
    const int bb  = blockIdx.z;
    const int ib0 = blockIdx.y * 128;
    const int jb0 = blockIdx.x * 128;
    const int na  = g_cntA[bb];
    const int nb  = g_cntB[bb];
    if (ib0 >= na || jb0 >= nb) return;

    __shared__ __align__(16) __nv_bfloat16 sm[4 * 128 * RS];  // 40960B
    __nv_bfloat16* sAh = sm;
    __nv_bfloat16* sAl = sAh + 128 * RS;
    __nv_bfloat16* sBh = sAl + 128 * RS;
    __nv_bfloat16* sBl = sBh + 128 * RS;
    float* tbuf = (float*)sm;  // reused post-MMA

    const int t    = threadIdx.x;
    const int lane = t & 31;
    const int wid  = t >> 5;
    const int wm   = wid >> 1;   // 0..3
    const int wn   = wid & 1;    // 0..1
    const int gq   = lane >> 2;

    const int lrow = (lane & 7) + ((lane >> 3) & 1) * 8;
    const int lcol = (lane >> 4) * 8;

    const uint32_t sAh_u = smem_u32(sAh), sAl_u = smem_u32(sAl);
    const uint32_t sBh_u = smem_u32(sBh), sBl_u = smem_u32(sBl);

    float c[2][8][4];
#pragma unroll
    for (int mf = 0; mf < 2; mf++)
#pragma unroll
        for (int nf = 0; nf < 8; nf++)
#pragma unroll
            for (int v = 0; v < 4; v++) c[mf][nf][v] = 0.f;

    const size_t aBase = ((size_t)bb * NL + ib0) * ND;
    const size_t bBase = ((size_t)bb * NL + jb0) * ND;
    // cp.async mapping: 2 passes, each 128 rows x 4 x 16B segments per array
    const int cprow0 = t >> 2;          // +64 per pass
    const int cpc8   = (t & 3) * 8;     // bf16 col (8 per 16B)

    // issue chunk 0
#pragma unroll
    for (int p = 0; p < 2; p++) {
        int row = cprow0 + 64 * p;
        size_t go = (size_t)row * ND + cpc8;
        uint32_t so = (uint32_t)((row * RS + cpc8) * 2);
        cpasync16(sAh_u + so, &g_Ahi[aBase + go]);
        cpasync16(sAl_u + so, &g_Alo[aBase + go]);
        cpasync16(sBh_u + so, &g_Bhi[bBase + go]);
        cpasync16(sBl_u + so, &g_Blo[bBase + go]);
    }
    cpasync_commit();

#pragma unroll 1
    for (int kc = 0; kc < ND; kc += 32) {
        cpasync_wait0();
        __syncthreads();
#pragma unroll
        for (int term = 0; term < 3; term++) {
            const uint32_t au = (term == 2) ? sAl_u : sAh_u;
            const uint32_t bu = (term == 1) ? sBl_u : sBh_u;
#pragma unroll
            for (int k0 = 0; k0 < 32; k0 += 16) {
                uint32_t b0[8], b1[8];
#pragma unroll
                for (int nfp = 0; nfp < 4; nfp++) {
                    uint32_t addr = bu +
                        (uint32_t)(((wn * 64 + nfp * 16 + lrow) * RS + k0 + lcol) * 2);
                    ldsm_x4(b0[2 * nfp], b0[2 * nfp + 1], b1[2 * nfp], b1[2 * nfp + 1], addr);
                }
#pragma unroll
                for (int mf = 0; mf < 2; mf++) {
                    uint32_t a0, a1, a2, a3;
                    uint32_t addrA = au +
                        (uint32_t)(((wm * 32 + mf * 16 + lrow) * RS + k0 + lcol) * 2);
                    ldsm_x4(a0, a1, a2, a3, addrA);
#pragma unroll
                    for (int nf = 0; nf < 8; nf++)
                        mma_bf16(c[mf][nf], a0, a1, a2, a3, b0[nf], b1[nf]);
                }
            }
        }
        __syncthreads();
        if (kc + 32 < ND) {
#pragma unroll
            for (int p = 0; p < 2; p++) {
                int row = cprow0 + 64 * p;
                size_t go = (size_t)row * ND + kc + 32 + cpc8;
                uint32_t so = (uint32_t)((row * RS + cpc8) * 2);
                cpasync16(sAh_u + so, &g_Ahi[aBase + go]);
                cpasync16(sAl_u + so, &g_Alo[aBase + go]);
                cpasync16(sBh_u + so, &g_Bhi[bBase + go]);
                cpasync16(sBl_u + so, &g_Blo[bBase + go]);
            }
            cpasync_commit();
        }
    }

    // ---- epilogue 1: direct store to g_S
#pragma unroll
    for (int mf = 0; mf < 2; mf++)
#pragma unroll
        for (int nf = 0; nf < 8; nf++) {
            int r  = ib0 + wm * 32 + mf * 16 + gq;
            int jj = jb0 + wn * 64 + nf * 8 + 2 * (lane & 3);
            *(float2*)&g_S[((size_t)(bb * NL) + r) * NL + jj] =
                make_float2(c[mf][nf][0], c[mf][nf][1]);
            *(float2*)&g_S[((size_t)(bb * NL) + r + 8) * NL + jj] =
                make_float2(c[mf][nf][2], c[mf][nf][3]);
        }

    // ---- epilogue 2: transpose to g_ST via smem, 4 passes of 32 j-cols
#pragma unroll 1
    for (int p = 0; p < 4; p++) {
        __syncthreads();
        if (wn == (p >> 1)) {
            int nfb = (p & 1) * 4;
#pragma unroll
            for (int mf = 0; mf < 2; mf++)
#pragma unroll
                for (int nfo = 0; nfo < 4; nfo++) {
                    int nf = nfb + nfo;
                    int jl = wn * 64 + nf * 8 + 2 * (lane & 3) - p * 32;
                    int il = wm * 32 + mf * 16 + gq;
                    tbuf[jl * 132 + il]           = c[mf][nf][0];
                    tbuf[(jl + 1) * 132 + il]     = c[mf][nf][1];
                    tbuf[jl * 132 + il + 8]       = c[mf][nf][2];
                    tbuf[(jl + 1) * 132 + il + 8] = c[mf][nf][3];
                }
        }
        __syncthreads();
#pragma unroll
        for (int q = 0; q < 4; q++) {
            int id  = t + 256 * q;
            int jl  = id >> 5;
            int il4 = (id & 31) * 4;
            int gj  = jb0 + p * 32 + jl;
            *(float4*)&g_ST[((size_t)(bb * NL) + gj) * NL + ib0 + il4] =
                *(float4*)&tbuf[jl * 132 + il4];
        }
    }
}

// ---------------------------------------------------------------------------
// K2: softmax stats, row-wise scans on g_S (which=0) or g_ST (which=1).
// ---------------------------------------------------------------------------
__global__ void __launch_bounds__(256) k2_stats(int which) {
    const int warp  = threadIdx.x >> 5;
    const int lane  = threadIdx.x & 31;
    const int rowid = blockIdx.x * 8 + warp;
    const int bb    = rowid >> 10;
    const int r     = rowid & (NL - 1);
    const int cntM  = which ? g_cntB[bb] : g_cntA[bb];
    const int cntK  = which ? g_cntA[bb] : g_cntB[bb];
    if (r >= cntM) return;
    const float* Srow = (which ? g_ST : g_S) + (size_t)rowid * NL;
    float* oMax = which ? g_colMax : g_rowMax;
    float* oSc  = which ? g_colScale : g_rowScale;

    const int k4 = cntK & ~3;
    float m = -INFINITY;
    for (int j = lane * 4; j < k4; j += 128) {
        float4 v = *(const float4*)(Srow + j);
        m = fmaxf(m, fmaxf(fmaxf(v.x, v.y), fmaxf(v.z, v.w)));
    }
    for (int j = k4 + lane; j < cntK; j += 32) m = fmaxf(m, Srow[j]);
#pragma unroll
    for (int o = 16; o > 0; o >>= 1) m = fmaxf(m, __shfl_xor_sync(0xffffffffu, m, o));

    float s = 0.f;
    if (m != -INFINITY) {
        for (int j = lane * 4; j < k4; j += 128) {
            float4 v = *(const float4*)(Srow + j);
            s += __expf(v.x - m) + __expf(v.y - m) + __expf(v.z - m) + __expf(v.w - m);
        }
        for (int j = k4 + lane; j < cntK; j += 32) s += __expf(Srow[j] - m);
    }
#pragma unroll
    for (int o = 16; o > 0; o >>= 1) s += __shfl_xor_sync(0xffffffffu, s, o);

    if (lane == 0) {
        if (m == -INFINITY) { oMax[rowid] = 0.f; oSc[rowid] = 0.f; }
        else                { oMax[rowid] = m;   oSc[rowid] = 1.f / s; }
    }
}

// ---------------------------------------------------------------------------
// K3: attended = softmax-weights @ values, 3-term bf16 mma.sync,
// ldmatrix fragments, V staged via cp.async, W computed in store phase.
// ---------------------------------------------------------------------------
__global__ void __launch_bounds__(256, 2) k3_mma(int which, float* __restrict__ out) {
    const int bb  = blockIdx.z;
    const int m0  = blockIdx.y * 128;
    const int db0 = blockIdx.x * 128;
    const int cntM = which ? g_cntB[bb] : g_cntA[bb];
    const int cntK = which ? g_cntA[bb] : g_cntB[bb];
    if (m0 >= cntM) return;

    const float* Sarr = which ? g_ST : g_S;
    const float* stM  = which ? g_colMax : g_rowMax;
    const float* stSc = which ? g_colScale : g_rowScale;
    const __nv_bfloat16* VhT = which ? g_AhiT : g_BhiT;
    const __nv_bfloat16* VlT = which ? g_AloT : g_BloT;
    const int* idxOut = (which ? g_idxB : g_idxA) + bb * NL;

    __shared__ __align__(16) __nv_bfloat16 smh[4 * 128 * RS];
    __nv_bfloat16* sWh = smh;
    __nv_bfloat16* sWl = sWh + 128 * RS;
    __nv_bfloat16* sVh = sWl + 128 * RS;
    __nv_bfloat16* sVl = sVh + 128 * RS;
    __shared__ float sM[128], sSc[128];
    __shared__ int   sIdx[128];

    const int t    = threadIdx.x;
    const int lane = t & 31;
    const int wid  = t >> 5;
    const int wm   = wid >> 1;
    const int wn   = wid & 1;
    const int gq   = lane >> 2;

    const int lrow = (lane & 7) + ((lane >> 3) & 1) * 8;
    const int lcol = (lane >> 4) * 8;

    const uint32_t sWh_u = smem_u32(sWh), sWl_u = smem_u32(sWl);
    const uint32_t sVh_u = smem_u32(sVh), sVl_u = smem_u32(sVl);

    if (t < 128) {
        sM[t]   = stM[bb * NL + m0 + t];
        sSc[t]  = stSc[bb * NL + m0 + t];
        sIdx[t] = idxOut[m0 + t];
    }
    __syncthreads();

    float c[2][8][4];
#pragma unroll
    for (int mf = 0; mf < 2; mf++)
#pragma unroll
        for (int nf = 0; nf < 8; nf++)
#pragma unroll
            for (int v = 0; v < 4; v++) c[mf][nf][v] = 0.f;

    const size_t sBase = ((size_t)bb * NL + m0) * NL;
    const size_t vBase = ((size_t)bb * ND + db0) * NL;
    const int kend = (cntK + 31) & ~31;
    const int lr0 = t >> 3;          // W-phase rows (+32 per q)
    const int lc0 = (t & 7) * 4;
    const int cprow0 = t >> 2;       // V cp.async rows (+64 per pass)
    const int cpc8   = (t & 3) * 8;

    // issue V chunk 0
#pragma unroll
    for (int p = 0; p < 2; p++) {
        int row = cprow0 + 64 * p;
        size_t go = vBase + (size_t)row * NL + cpc8;
        uint32_t so = (uint32_t)((row * RS + cpc8) * 2);
        cpasync16(sVh_u + so, &VhT[go]);
        cpasync16(sVl_u + so, &VlT[go]);
    }
    cpasync_commit();

#pragma unroll 1
    for (int kc = 0; kc < kend; kc += 32) {
        // W store phase (buffer free since prev post-MMA sync)
#pragma unroll
        for (int q = 0; q < 4; q++) {
            int row = lr0 + 32 * q;
            float4 v = *(const float4*)&Sarr[sBase + (size_t)row * NL + kc + lc0];
            float mrq = sM[row];
            float w0 = (kc + lc0 + 0 < cntK) ? __expf(v.x - mrq) : 0.f;
            float w1 = (kc + lc0 + 1 < cntK) ? __expf(v.y - mrq) : 0.f;
            float w2 = (kc + lc0 + 2 < cntK) ? __expf(v.z - mrq) : 0.f;
            float w3 = (kc + lc0 + 3 < cntK) ? __expf(v.w - mrq) : 0.f;
            __nv_bfloat16 h0 = __float2bfloat16(w0), h1 = __float2bfloat16(w1);
            __nv_bfloat16 h2 = __float2bfloat16(w2), h3 = __float2bfloat16(w3);
            int so = row * RS + lc0;
            sWh[so + 0] = h0; sWh[so + 1] = h1; sWh[so + 2] = h2; sWh[so + 3] = h3;
            sWl[so + 0] = __float2bfloat16(w0 - __bfloat162float(h0));
            sWl[so + 1] = __float2bfloat16(w1 - __bfloat162float(h1));
            sWl[so + 2] = __float2bfloat16(w2 - __bfloat162float(h2));
            sWl[so + 3] = __float2bfloat16(w3 - __bfloat162float(h3));
        }
        cpasync_wait0();
        __syncthreads();
#pragma unroll
        for (int term = 0; term < 3; term++) {
            const uint32_t au = (term == 2) ? sWl_u : sWh_u;
            const uint32_t bu = (term == 1) ? sVl_u : sVh_u;
#pragma unroll
            for (int k0 = 0; k0 < 32; k0 += 16) {
                uint32_t b0[8], b1[8];
#pragma unroll
                for (int nfp = 0; nfp < 4; nfp++) {
                    uint32_t addr = bu +
                        (uint32_t)(((wn * 64 + nfp * 16 + lrow) * RS + k0 + lcol) * 2);
                    ldsm_x4(b0[2 * nfp], b0[2 * nfp + 1], b1[2 * nfp], b1[2 * nfp + 1], addr);
                }
#pragma unroll
                for (int mf = 0; mf < 2; mf++) {
                    uint32_t a0, a1, a2, a3;
                    uint32_t addrA = au +
                        (uint32_t)(((wm * 32 + mf * 16 + lrow) * RS + k0 + lcol) * 2);
                    ldsm_x4(a0, a1, a2, a3, addrA);
#pragma unroll
                    for (int nf = 0; nf < 8; nf++)
                        mma_bf16(c[mf][nf], a0, a1, a2, a3, b0[nf], b1[nf]);
                }
            }
        }
        __syncthreads();
        if (kc + 32 < kend) {
#pragma unroll
            for (int p = 0; p < 2; p++) {
                int row = cprow0 + 64 * p;
                size_t go = vBase + (size_t)row * NL + kc + 32 + cpc8;
                uint32_t so = (uint32_t)((row * RS + cpc8) * 2);
                cpasync16(sVh_u + so, &VhT[go]);
                cpasync16(sVl_u + so, &VlT[go]);
            }
            cpasync_commit();
        }
    }

    // ---- epilogue: scale + scatter
#pragma unroll
    for (int mf = 0; mf < 2; mf++) {
        int rl = wm * 32 + mf * 16 + gq;
#pragma unroll
        for (int nf = 0; nf < 8; nf++) {
            int jj = db0 + wn * 64 + nf * 8 + 2 * (lane & 3);
            if (m0 + rl < cntM) {
                float sc = sSc[rl];
                *(float2*)&out[((size_t)(bb * NL) + sIdx[rl]) * ND + jj] =
                    make_float2(c[mf][nf][0] * sc, c[mf][nf][1] * sc);
            }
            if (m0 + rl + 8 < cntM) {
                float sc = sSc[rl + 8];
                *(float2*)&out[((size_t)(bb * NL) + sIdx[rl + 8]) * ND + jj] =
                    make_float2(c[mf][nf][2] * sc, c[mf][nf][3] * sc);
            }
        }
    }
}

// ---------------------------------------------------------------------------
extern "C" void kernel_launch(void* const* d_in, const int* in_sizes, int n_in,
                              void* d_out, int out_size) {
    const float* a      = (const float*)d_in[0];
    const float* b      = (const float*)d_in[1];
    const int*   mask_a = (const int*)d_in[2];
    const int*   mask_b = (const int*)d_in[3];
    float* outA = (float*)d_out;
    float* outB = outA + (size_t)NB * NL * ND;

    cudaMemsetAsync(d_out, 0, (size_t)out_size * sizeof(float));

    k0_compact<<<64, 1024>>>(mask_a, mask_b);
    k_conv<<<dim3(8, 32, 64), 256>>>(a, b);
    k1_mma<<<dim3(8, 8, NB), 256>>>();
    k2_stats<<<NB * NL / 8, 256>>>(0);
    k2_stats<<<NB * NL / 8, 256>>>(1);
    k3_mma<<<dim3(2, 8, NB), 256>>>(0, outA);
    k3_mma<<<dim3(2, 8, NB), 256>>>(1, outB);
}

// round 8
// speedup vs baseline: 5.0695x; 1.0321x over previous
#include <cuda_runtime.h>
#include <cuda_bf16.h>
#include <math.h>
#include <cstdint>

// Problem constants
constexpr int NB = 32;    // batch
constexpr int NL = 1024;  // La = Lb
constexpr int ND = 256;   // feature dim

// Scratch
__device__ float g_S [(size_t)NB * NL * NL];   // logits, compact [i][j]
__device__ float g_ST[(size_t)NB * NL * NL];   // logits transposed, compact [j][i]
__device__ float g_rowMax[NB * NL];
__device__ float g_rowScale[NB * NL];
__device__ float g_colMax[NB * NL];
__device__ float g_colScale[NB * NL];
__device__ int   g_idxA[NB * NL];
__device__ int   g_idxB[NB * NL];
__device__ int   g_cntA[NB];
__device__ int   g_cntB[NB];

// Compacted bf16 hi/lo copies of a, b (row = compact position), plus transposed.
__device__ __nv_bfloat16 g_Ahi [(size_t)NB * NL * ND];
__device__ __nv_bfloat16 g_Alo [(size_t)NB * NL * ND];
__device__ __nv_bfloat16 g_Bhi [(size_t)NB * NL * ND];
__device__ __nv_bfloat16 g_Blo [(size_t)NB * NL * ND];
__device__ __nv_bfloat16 g_AhiT[(size_t)NB * ND * NL];   // [d][i_compact]
__device__ __nv_bfloat16 g_AloT[(size_t)NB * ND * NL];
__device__ __nv_bfloat16 g_BhiT[(size_t)NB * ND * NL];   // [d][j_compact]
__device__ __nv_bfloat16 g_BloT[(size_t)NB * ND * NL];

constexpr int RS = 40;  // smem bf16 row stride (32 data + 8 pad); 80B rows -> LDSM conflict-free

// m16n8k16 bf16 MMA, fp32 accumulate
__device__ __forceinline__ void mma_bf16(float* c, uint32_t a0, uint32_t a1,
                                         uint32_t a2, uint32_t a3,
                                         uint32_t b0, uint32_t b1) {
    asm volatile(
        "mma.sync.aligned.m16n8k16.row.col.f32.bf16.bf16.f32 "
        "{%0,%1,%2,%3}, {%4,%5,%6,%7}, {%8,%9}, {%0,%1,%2,%3};"
        : "+f"(c[0]), "+f"(c[1]), "+f"(c[2]), "+f"(c[3])
        : "r"(a0), "r"(a1), "r"(a2), "r"(a3), "r"(b0), "r"(b1));
}

__device__ __forceinline__ void ldsm_x4(uint32_t& r0, uint32_t& r1,
                                        uint32_t& r2, uint32_t& r3, uint32_t addr) {
    asm volatile("ldmatrix.sync.aligned.m8n8.x4.shared.b16 {%0,%1,%2,%3}, [%4];"
        : "=r"(r0), "=r"(r1), "=r"(r2), "=r"(r3) : "r"(addr));
}

__device__ __forceinline__ uint32_t smem_u32(const void* p) {
    uint32_t a;
    asm("{ .reg .u64 tmp; cvta.to.shared.u64 tmp, %1; cvt.u32.u64 %0, tmp; }"
        : "=r"(a) : "l"(p));
    return a;
}

__device__ __forceinline__ void cpasync16(uint32_t saddr, const void* gptr) {
    asm volatile("cp.async.cg.shared.global [%0], [%1], 16;"
        :: "r"(saddr), "l"(gptr) : "memory");
}
__device__ __forceinline__ void cpasync_commit() {
    asm volatile("cp.async.commit_group;" ::: "memory");
}
__device__ __forceinline__ void cpasync_wait0() {
    asm volatile("cp.async.wait_group 0;" ::: "memory");
}

__device__ __forceinline__ uint32_t bf2_as_u32(__nv_bfloat162 v) {
    return *(uint32_t*)&v;
}

// ---------------------------------------------------------------------------
// K0: per-batch mask compaction (idx padded to 1024 with last valid index).
// ---------------------------------------------------------------------------
__global__ void __launch_bounds__(1024) k0_compact(const int* __restrict__ mask_a,
                                                   const int* __restrict__ mask_b) {
    const int which = blockIdx.x >> 5;
    const int bb    = blockIdx.x & 31;
    const int* m = (which ? mask_b : mask_a) + bb * NL;
    int* idx = (which ? g_idxB : g_idxA) + bb * NL;
    int* cnt = which ? g_cntB : g_cntA;
    const int t = threadIdx.x, lane = t & 31, w = t >> 5;

    int mv = (m[t] != 0);
    unsigned bal = __ballot_sync(0xffffffffu, mv);
    int pw = __popc(bal & ((1u << lane) - 1));
    __shared__ int wc[32];
    if (lane == 0) wc[w] = __popc(bal);
    __syncthreads();
    if (t < 32) {
        int v = wc[t];
#pragma unroll
        for (int o = 1; o < 32; o <<= 1) {
            int u = __shfl_up_sync(0xffffffffu, v, o);
            if (lane >= o) v += u;
        }
        wc[t] = v;
    }
    __syncthreads();
    const int base  = (w == 0) ? 0 : wc[w - 1];
    const int total = wc[31];
    if (mv) idx[base + pw] = t;
    if (t == 0) cnt[bb] = total;
    __syncthreads();
    __shared__ int lastIdx;
    if (t == 0) lastIdx = (total > 0) ? idx[total - 1] : 0;
    __syncthreads();
    if (t >= total) idx[t] = lastIdx;
}

// ---------------------------------------------------------------------------
// KC: gather-compact + fp32->bf16 hi/lo split + transpose.
// Early-exits row-tiles beyond roundup(cnt,128) (never read downstream).
// ---------------------------------------------------------------------------
__global__ void __launch_bounds__(256) k_conv(const float* __restrict__ a,
                                              const float* __restrict__ b) {
    const int z     = blockIdx.z;
    const int which = z >> 5;               // 0: a, 1: b
    const int bb    = z & 31;
    const int dt    = blockIdx.x * 32;
    const int rt    = blockIdx.y * 32;
    const int cnt   = which ? g_cntB[bb] : g_cntA[bb];
    if (rt >= ((cnt + 127) & ~127)) return;
    const float* src = which ? b : a;
    const int* idx   = (which ? g_idxB : g_idxA) + bb * NL;
    __nv_bfloat16* oH  = which ? g_Bhi  : g_Ahi;
    __nv_bfloat16* oL  = which ? g_Blo  : g_Alo;
    __nv_bfloat16* oHT = which ? g_BhiT : g_AhiT;
    __nv_bfloat16* oLT = which ? g_BloT : g_AloT;

    const int tx = threadIdx.x & 31;
    const int ty = threadIdx.x >> 5;
    __shared__ float tile[32][33];

#pragma unroll
    for (int rr = 0; rr < 4; rr++) {
        int rl = ty + 8 * rr;
        int grow = idx[rt + rl];
        float v = src[((size_t)bb * NL + grow) * ND + dt + tx];
        tile[rl][tx] = v;
        __nv_bfloat16 h = __float2bfloat16(v);
        __nv_bfloat16 l = __float2bfloat16(v - __bfloat162float(h));
        size_t o = ((size_t)bb * NL + rt + rl) * ND + dt + tx;
        oH[o] = h; oL[o] = l;
    }
    __syncthreads();
#pragma unroll
    for (int rr = 0; rr < 4; rr++) {
        int dl = ty + 8 * rr;
        float v = tile[tx][dl];
        __nv_bfloat16 h = __float2bfloat16(v);
        __nv_bfloat16 l = __float2bfloat16(v - __bfloat162float(h));
        size_t o = ((size_t)bb * ND + dt + dl) * NL + rt + tx;
        oHT[o] = h; oLT[o] = l;
    }
}

// ---------------------------------------------------------------------------
// K1: S = a_c @ b_c^T (compact), 3-term bf16 mma.sync with ldmatrix +
// cp.async staged loads (low reg pressure, 2 CTAs/SM). Writes g_S AND g_ST.
// ---------------------------------------------------------------------------
__global__ void __launch_bounds__(256, 2) k1_mma() {
    const int bb  = blockIdx.z;
    const int ib0 = blockIdx.y * 128;
    const int jb0 = blockIdx.x * 128;
    const int na  = g_cntA[bb];
    const int nb  = g_cntB[bb];
    if (ib0 >= na || jb0 >= nb) return;

    __shared__ __align__(16) __nv_bfloat16 sm[4 * 128 * RS];  // 40960B
    __nv_bfloat16* sAh = sm;
    __nv_bfloat16* sAl = sAh + 128 * RS;
    __nv_bfloat16* sBh = sAl + 128 * RS;
    __nv_bfloat16* sBl = sBh + 128 * RS;
    float* tbuf = (float*)sm;  // reused post-MMA

    const int t    = threadIdx.x;
    const int lane = t & 31;
    const int wid  = t >> 5;
    const int wm   = wid >> 1;   // 0..3
    const int wn   = wid & 1;    // 0..1
    const int gq   = lane >> 2;

    const int lrow = (lane & 7) + ((lane >> 3) & 1) * 8;
    const int lcol = (lane >> 4) * 8;

    const uint32_t sAh_u = smem_u32(sAh), sAl_u = smem_u32(sAl);
    const uint32_t sBh_u = smem_u32(sBh), sBl_u = smem_u32(sBl);

    float c[2][8][4];
#pragma unroll
    for (int mf = 0; mf < 2; mf++)
#pragma unroll
        for (int nf = 0; nf < 8; nf++)
#pragma unroll
            for (int v = 0; v < 4; v++) c[mf][nf][v] = 0.f;

    const size_t aBase = ((size_t)bb * NL + ib0) * ND;
    const size_t bBase = ((size_t)bb * NL + jb0) * ND;
    const int cprow0 = t >> 2;          // +64 per pass
    const int cpc8   = (t & 3) * 8;     // bf16 col (8 per 16B)

    // issue chunk 0
#pragma unroll
    for (int p = 0; p < 2; p++) {
        int row = cprow0 + 64 * p;
        size_t go = (size_t)row * ND + cpc8;
        uint32_t so = (uint32_t)((row * RS + cpc8) * 2);
        cpasync16(sAh_u + so, &g_Ahi[aBase + go]);
        cpasync16(sAl_u + so, &g_Alo[aBase + go]);
        cpasync16(sBh_u + so, &g_Bhi[bBase + go]);
        cpasync16(sBl_u + so, &g_Blo[bBase + go]);
    }
    cpasync_commit();

#pragma unroll 1
    for (int kc = 0; kc < ND; kc += 32) {
        cpasync_wait0();
        __syncthreads();
#pragma unroll
        for (int term = 0; term < 3; term++) {
            const uint32_t au = (term == 2) ? sAl_u : sAh_u;
            const uint32_t bu = (term == 1) ? sBl_u : sBh_u;
#pragma unroll
            for (int k0 = 0; k0 < 32; k0 += 16) {
                uint32_t b0[8], b1[8];
#pragma unroll
                for (int nfp = 0; nfp < 4; nfp++) {
                    uint32_t addr = bu +
                        (uint32_t)(((wn * 64 + nfp * 16 + lrow) * RS + k0 + lcol) * 2);
                    ldsm_x4(b0[2 * nfp], b0[2 * nfp + 1], b1[2 * nfp], b1[2 * nfp + 1], addr);
                }
#pragma unroll
                for (int mf = 0; mf < 2; mf++) {
                    uint32_t a0, a1, a2, a3;
                    uint32_t addrA = au +
                        (uint32_t)(((wm * 32 + mf * 16 + lrow) * RS + k0 + lcol) * 2);
                    ldsm_x4(a0, a1, a2, a3, addrA);
#pragma unroll
                    for (int nf = 0; nf < 8; nf++)
                        mma_bf16(c[mf][nf], a0, a1, a2, a3, b0[nf], b1[nf]);
                }
            }
        }
        __syncthreads();
        if (kc + 32 < ND) {
#pragma unroll
            for (int p = 0; p < 2; p++) {
                int row = cprow0 + 64 * p;
                size_t go = (size_t)row * ND + kc + 32 + cpc8;
                uint32_t so = (uint32_t)((row * RS + cpc8) * 2);
                cpasync16(sAh_u + so, &g_Ahi[aBase + go]);
                cpasync16(sAl_u + so, &g_Alo[aBase + go]);
                cpasync16(sBh_u + so, &g_Bhi[bBase + go]);
                cpasync16(sBl_u + so, &g_Blo[bBase + go]);
            }
            cpasync_commit();
        }
    }

    // ---- epilogue 1: direct store to g_S
#pragma unroll
    for (int mf = 0; mf < 2; mf++)
#pragma unroll
        for (int nf = 0; nf < 8; nf++) {
            int r  = ib0 + wm * 32 + mf * 16 + gq;
            int jj = jb0 + wn * 64 + nf * 8 + 2 * (lane & 3);
            *(float2*)&g_S[((size_t)(bb * NL) + r) * NL + jj] =
                make_float2(c[mf][nf][0], c[mf][nf][1]);
            *(float2*)&g_S[((size_t)(bb * NL) + r + 8) * NL + jj] =
                make_float2(c[mf][nf][2], c[mf][nf][3]);
        }

    // ---- epilogue 2: transpose to g_ST via smem, 4 passes of 32 j-cols
#pragma unroll 1
    for (int p = 0; p < 4; p++) {
        __syncthreads();
        if (wn == (p >> 1)) {
            int nfb = (p & 1) * 4;
#pragma unroll
            for (int mf = 0; mf < 2; mf++)
#pragma unroll
                for (int nfo = 0; nfo < 4; nfo++) {
                    int nf = nfb + nfo;
                    int jl = wn * 64 + nf * 8 + 2 * (lane & 3) - p * 32;
                    int il = wm * 32 + mf * 16 + gq;
                    tbuf[jl * 132 + il]           = c[mf][nf][0];
                    tbuf[(jl + 1) * 132 + il]     = c[mf][nf][1];
                    tbuf[jl * 132 + il + 8]       = c[mf][nf][2];
                    tbuf[(jl + 1) * 132 + il + 8] = c[mf][nf][3];
                }
        }
        __syncthreads();
#pragma unroll
        for (int q = 0; q < 4; q++) {
            int id  = t + 256 * q;
            int jl  = id >> 5;
            int il4 = (id & 31) * 4;
            int gj  = jb0 + p * 32 + jl;
            *(float4*)&g_ST[((size_t)(bb * NL) + gj) * NL + ib0 + il4] =
                *(float4*)&tbuf[jl * 132 + il4];
        }
    }
}

// ---------------------------------------------------------------------------
// K2: softmax stats; both orientations in ONE launch (which = blockIdx.y).
// ---------------------------------------------------------------------------
__global__ void __launch_bounds__(256) k2_stats() {
    const int which = blockIdx.y;
    const int warp  = threadIdx.x >> 5;
    const int lane  = threadIdx.x & 31;
    const int rowid = blockIdx.x * 8 + warp;
    const int bb    = rowid >> 10;
    const int r     = rowid & (NL - 1);
    const int cntM  = which ? g_cntB[bb] : g_cntA[bb];
    const int cntK  = which ? g_cntA[bb] : g_cntB[bb];
    if (r >= cntM) return;
    const float* Srow = (which ? g_ST : g_S) + (size_t)rowid * NL;
    float* oMax = which ? g_colMax : g_rowMax;
    float* oSc  = which ? g_colScale : g_rowScale;

    const int k4 = cntK & ~3;
    float m = -INFINITY;
    for (int j = lane * 4; j < k4; j += 128) {
        float4 v = *(const float4*)(Srow + j);
        m = fmaxf(m, fmaxf(fmaxf(v.x, v.y), fmaxf(v.z, v.w)));
    }
    for (int j = k4 + lane; j < cntK; j += 32) m = fmaxf(m, Srow[j]);
#pragma unroll
    for (int o = 16; o > 0; o >>= 1) m = fmaxf(m, __shfl_xor_sync(0xffffffffu, m, o));

    float s = 0.f;
    if (m != -INFINITY) {
        for (int j = lane * 4; j < k4; j += 128) {
            float4 v = *(const float4*)(Srow + j);
            s += __expf(v.x - m) + __expf(v.y - m) + __expf(v.z - m) + __expf(v.w - m);
        }
        for (int j = k4 + lane; j < cntK; j += 32) s += __expf(Srow[j] - m);
    }
#pragma unroll
    for (int o = 16; o > 0; o >>= 1) s += __shfl_xor_sync(0xffffffffu, s, o);

    if (lane == 0) {
        if (m == -INFINITY) { oMax[rowid] = 0.f; oSc[rowid] = 0.f; }
        else                { oMax[rowid] = m;   oSc[rowid] = 1.f / s; }
    }
}

// ---------------------------------------------------------------------------
// K3: attended = softmax-weights @ values; BOTH directions in one launch.
// blockIdx.z: bb = z&31, which = z>>5.  W stores packed 64-bit.
// ---------------------------------------------------------------------------
__global__ void __launch_bounds__(256, 2) k3_mma(float* __restrict__ outA,
                                                 float* __restrict__ outB) {
    const int z    = blockIdx.z;
    const int which = z >> 5;
    const int bb   = z & 31;
    const int m0   = blockIdx.y * 128;
    const int db0  = blockIdx.x * 128;
    const int cntM = which ? g_cntB[bb] : g_cntA[bb];
    const int cntK = which ? g_cntA[bb] : g_cntB[bb];
    if (m0 >= cntM) return;
    float* out = which ? outB : outA;

    const float* Sarr = which ? g_ST : g_S;
    const float* stM  = which ? g_colMax : g_rowMax;
    const float* stSc = which ? g_colScale : g_rowScale;
    const __nv_bfloat16* VhT = which ? g_AhiT : g_BhiT;
    const __nv_bfloat16* VlT = which ? g_AloT : g_BloT;
    const int* idxOut = (which ? g_idxB : g_idxA) + bb * NL;

    __shared__ __align__(16) __nv_bfloat16 smh[4 * 128 * RS];
    __nv_bfloat16* sWh = smh;
    __nv_bfloat16* sWl = sWh + 128 * RS;
    __nv_bfloat16* sVh = sWl + 128 * RS;
    __nv_bfloat16* sVl = sVh + 128 * RS;
    __shared__ float sM[128], sSc[128];
    __shared__ int   sIdx[128];

    const int t    = threadIdx.x;
    const int lane = t & 31;
    const int wid  = t >> 5;
    const int wm   = wid >> 1;
    const int wn   = wid & 1;
    const int gq   = lane >> 2;

    const int lrow = (lane & 7) + ((lane >> 3) & 1) * 8;
    const int lcol = (lane >> 4) * 8;

    const uint32_t sWh_u = smem_u32(sWh), sWl_u = smem_u32(sWl);
    const uint32_t sVh_u = smem_u32(sVh), sVl_u = smem_u32(sVl);

    if (t < 128) {
        sM[t]   = stM[bb * NL + m0 + t];
        sSc[t]  = stSc[bb * NL + m0 + t];
        sIdx[t] = idxOut[m0 + t];
    }
    __syncthreads();

    float c[2][8][4];
#pragma unroll
    for (int mf = 0; mf < 2; mf++)
#pragma unroll
        for (int nf = 0; nf < 8; nf++)
#pragma unroll
            for (int v = 0; v < 4; v++) c[mf][nf][v] = 0.f;

    const size_t sBase = ((size_t)bb * NL + m0) * NL;
    const size_t vBase = ((size_t)bb * ND + db0) * NL;
    const int kend = (cntK + 31) & ~31;
    const int lr0 = t >> 3;          // W-phase rows (+32 per q)
    const int lc0 = (t & 7) * 4;
    const int cprow0 = t >> 2;       // V cp.async rows (+64 per pass)
    const int cpc8   = (t & 3) * 8;

    // issue V chunk 0
#pragma unroll
    for (int p = 0; p < 2; p++) {
        int row = cprow0 + 64 * p;
        size_t go = vBase + (size_t)row * NL + cpc8;
        uint32_t so = (uint32_t)((row * RS + cpc8) * 2);
        cpasync16(sVh_u + so, &VhT[go]);
        cpasync16(sVl_u + so, &VlT[go]);
    }
    cpasync_commit();

#pragma unroll 1
    for (int kc = 0; kc < kend; kc += 32) {
        // W store phase: packed 64-bit smem stores
#pragma unroll
        for (int q = 0; q < 4; q++) {
            int row = lr0 + 32 * q;
            float4 v = *(const float4*)&Sarr[sBase + (size_t)row * NL + kc + lc0];
            float mrq = sM[row];
            float w0 = (kc + lc0 + 0 < cntK) ? __expf(v.x - mrq) : 0.f;
            float w1 = (kc + lc0 + 1 < cntK) ? __expf(v.y - mrq) : 0.f;
            float w2 = (kc + lc0 + 2 < cntK) ? __expf(v.z - mrq) : 0.f;
            float w3 = (kc + lc0 + 3 < cntK) ? __expf(v.w - mrq) : 0.f;
            __nv_bfloat162 h01 = __floats2bfloat162_rn(w0, w1);
            __nv_bfloat162 h23 = __floats2bfloat162_rn(w2, w3);
            __nv_bfloat162 l01 = __floats2bfloat162_rn(
                w0 - __bfloat162float(__low2bfloat16(h01)),
                w1 - __bfloat162float(__high2bfloat16(h01)));
            __nv_bfloat162 l23 = __floats2bfloat162_rn(
                w2 - __bfloat162float(__low2bfloat16(h23)),
                w3 - __bfloat162float(__high2bfloat16(h23)));
            int so = row * RS + lc0;
            *(uint2*)&sWh[so] = make_uint2(bf2_as_u32(h01), bf2_as_u32(h23));
            *(uint2*)&sWl[so] = make_uint2(bf2_as_u32(l01), bf2_as_u32(l23));
        }
        cpasync_wait0();
        __syncthreads();
#pragma unroll
        for (int term = 0; term < 3; term++) {
            const uint32_t au = (term == 2) ? sWl_u : sWh_u;
            const uint32_t bu = (term == 1) ? sVl_u : sVh_u;
#pragma unroll
            for (int k0 = 0; k0 < 32; k0 += 16) {
                uint32_t b0[8], b1[8];
#pragma unroll
                for (int nfp = 0; nfp < 4; nfp++) {
                    uint32_t addr = bu +
                        (uint32_t)(((wn * 64 + nfp * 16 + lrow) * RS + k0 + lcol) * 2);
                    ldsm_x4(b0[2 * nfp], b0[2 * nfp + 1], b1[2 * nfp], b1[2 * nfp + 1], addr);
                }
#pragma unroll
                for (int mf = 0; mf < 2; mf++) {
                    uint32_t a0, a1, a2, a3;
                    uint32_t addrA = au +
                        (uint32_t)(((wm * 32 + mf * 16 + lrow) * RS + k0 + lcol) * 2);
                    ldsm_x4(a0, a1, a2, a3, addrA);
#pragma unroll
                    for (int nf = 0; nf < 8; nf++)
                        mma_bf16(c[mf][nf], a0, a1, a2, a3, b0[nf], b1[nf]);
                }
            }
        }
        __syncthreads();
        if (kc + 32 < kend) {
#pragma unroll
            for (int p = 0; p < 2; p++) {
                int row = cprow0 + 64 * p;
                size_t go = vBase + (size_t)row * NL + kc + 32 + cpc8;
                uint32_t so = (uint32_t)((row * RS + cpc8) * 2);
                cpasync16(sVh_u + so, &VhT[go]);
                cpasync16(sVl_u + so, &VlT[go]);
            }
            cpasync_commit();
        }
    }

    // ---- epilogue: scale + scatter
#pragma unroll
    for (int mf = 0; mf < 2; mf++) {
        int rl = wm * 32 + mf * 16 + gq;
#pragma unroll
        for (int nf = 0; nf < 8; nf++) {
            int jj = db0 + wn * 64 + nf * 8 + 2 * (lane & 3);
            if (m0 + rl < cntM) {
                float sc = sSc[rl];
                *(float2*)&out[((size_t)(bb * NL) + sIdx[rl]) * ND + jj] =
                    make_float2(c[mf][nf][0] * sc, c[mf][nf][1] * sc);
            }
            if (m0 + rl + 8 < cntM) {
                float sc = sSc[rl + 8];
                *(float2*)&out[((size_t)(bb * NL) + sIdx[rl + 8]) * ND + jj] =
                    make_float2(c[mf][nf][2] * sc, c[mf][nf][3] * sc);
            }
        }
    }
}

// ---------------------------------------------------------------------------
extern "C" void kernel_launch(void* const* d_in, const int* in_sizes, int n_in,
                              void* d_out, int out_size) {
    const float* a      = (const float*)d_in[0];
    const float* b      = (const float*)d_in[1];
    const int*   mask_a = (const int*)d_in[2];
    const int*   mask_b = (const int*)d_in[3];
    float* outA = (float*)d_out;
    float* outB = outA + (size_t)NB * NL * ND;

    cudaMemsetAsync(d_out, 0, (size_t)out_size * sizeof(float));

    k0_compact<<<64, 1024>>>(mask_a, mask_b);
    k_conv<<<dim3(8, 32, 64), 256>>>(a, b);
    k1_mma<<<dim3(8, 8, NB), 256>>>();
    k2_stats<<<dim3(NB * NL / 8, 2), 256>>>();
    k3_mma<<<dim3(2, 8, 64), 256>>>(outA, outB);
}